// round 4
// baseline (speedup 1.0000x reference)
#include <cuda_runtime.h>

#define ALPHA   0.2f
#define NEG_BIG -9.0e15f

#define B_   8
#define N_   2048
#define F_   128

// Scratch (device globals — no allocation allowed in kernel_launch)
__device__ float g_Wh[B_ * N_ * F_];   // 32 MB
__device__ float g_s1[B_ * N_];
__device__ float g_s2[B_ * N_];
__device__ float g_s2t[N_ * B_];       // transposed s2: [j][b]
__device__ float g_m2[B_ * N_];        // masked row-max of s2

typedef unsigned long long u64;

// Packed fp32x2 FMA (sm_103a FFMA2): d = a*b + c element-wise.
__device__ __forceinline__ u64 ffma2(u64 a, u64 b, u64 c) {
    u64 d;
    asm("fma.rn.f32x2 %0, %1, %2, %3;" : "=l"(d) : "l"(a), "l"(b), "l"(c));
    return d;
}
__device__ __forceinline__ u64 dup2(float x) {
    u64 d;
    unsigned int xi = __float_as_uint(x);
    asm("mov.b64 %0, {%1, %2};" : "=l"(d) : "r"(xi), "r"(xi));
    return d;
}

// ---------------------------------------------------------------------------
// Kernel A: Wh = h @ W with packed FFMA2.
// ---------------------------------------------------------------------------
__global__ void __launch_bounds__(128) wh_gemm(const float* __restrict__ h,
                                               const float* __restrict__ W) {
    __shared__ float hs[64][32];
    __shared__ float Ws[32][128];
    const int tid = threadIdx.x;
    const int tx = tid & 15, ty = tid >> 4;
    const int i0 = blockIdx.x * 64;

    u64 acc[8][4];
    #pragma unroll
    for (int r = 0; r < 8; r++)
        #pragma unroll
        for (int c = 0; c < 4; c++) acc[r][c] = 0ULL;

    for (int k0 = 0; k0 < F_; k0 += 32) {
        #pragma unroll
        for (int p = 0; p < 4; p++) {
            int idx = tid + 128 * p;
            int r = idx >> 3;
            int c4 = idx & 7;
            *(float4*)&hs[r][c4 * 4] =
                *(const float4*)&h[(i0 + r) * F_ + k0 + c4 * 4];
        }
        #pragma unroll
        for (int p = 0; p < 8; p++) {
            int idx = tid + 128 * p;
            int r = idx >> 5;
            int c4 = idx & 31;
            *(float4*)&Ws[r][c4 * 4] =
                *(const float4*)&W[(k0 + r) * F_ + c4 * 4];
        }
        __syncthreads();
        #pragma unroll
        for (int kk = 0; kk < 32; kk++) {
            u64 av[8];
            #pragma unroll
            for (int r = 0; r < 8; r++) av[r] = dup2(hs[ty * 8 + r][kk]);
            ulonglong2 wa = *(ulonglong2*)&Ws[kk][tx * 8];
            ulonglong2 wb = *(ulonglong2*)&Ws[kk][tx * 8 + 4];
            #pragma unroll
            for (int r = 0; r < 8; r++) {
                acc[r][0] = ffma2(av[r], wa.x, acc[r][0]);
                acc[r][1] = ffma2(av[r], wa.y, acc[r][1]);
                acc[r][2] = ffma2(av[r], wb.x, acc[r][2]);
                acc[r][3] = ffma2(av[r], wb.y, acc[r][3]);
            }
        }
        __syncthreads();
    }
    #pragma unroll
    for (int r = 0; r < 8; r++) {
        int row = i0 + ty * 8 + r;
        ulonglong2 o0, o1;
        o0.x = acc[r][0]; o0.y = acc[r][1];
        o1.x = acc[r][2]; o1.y = acc[r][3];
        *(ulonglong2*)&g_Wh[row * F_ + tx * 8] = o0;
        *(ulonglong2*)&g_Wh[row * F_ + tx * 8 + 4] = o1;
    }
}

// ---------------------------------------------------------------------------
// Kernel B: s1/s2 = Wh·a1 / Wh·a2, plus transposed s2t[j][b].
// ---------------------------------------------------------------------------
__global__ void __launch_bounds__(256) compute_s(const float* __restrict__ a) {
    int row = blockIdx.x * 8 + (threadIdx.x >> 5);
    int lane = threadIdx.x & 31;
    float4 w  = *(const float4*)&g_Wh[row * F_ + lane * 4];
    float4 a1 = *(const float4*)&a[lane * 4];
    float4 a2 = *(const float4*)&a[F_ + lane * 4];
    float d1 = w.x * a1.x + w.y * a1.y + w.z * a1.z + w.w * a1.w;
    float d2 = w.x * a2.x + w.y * a2.y + w.z * a2.z + w.w * a2.w;
    #pragma unroll
    for (int o = 16; o > 0; o >>= 1) {
        d1 += __shfl_xor_sync(0xffffffffu, d1, o);
        d2 += __shfl_xor_sync(0xffffffffu, d2, o);
    }
    if (lane == 0) {
        g_s1[row] = d1;
        g_s2[row] = d2;
        int b = row >> 11;          // N_ = 2048
        int i = row & (N_ - 1);
        g_s2t[i * B_ + b] = d2;
    }
}

// ---------------------------------------------------------------------------
// Kernel B2: m2[b][i] = max over j with adj[i,j]>0 of s2[b][j].
// adj is batch-independent: one warp per adj row computes all 8 batch maxima.
// ---------------------------------------------------------------------------
__global__ void __launch_bounds__(256) row_max(const int* __restrict__ adj) {
    int i = blockIdx.x * 8 + (threadIdx.x >> 5);
    int lane = threadIdx.x & 31;
    float m[8];
    #pragma unroll
    for (int bb = 0; bb < 8; bb++) m[bb] = NEG_BIG;

    #pragma unroll 4
    for (int it = 0; it < N_ / 32; it++) {
        int j = it * 32 + lane;
        int ad = adj[i * N_ + j];
        if (ad > 0) {
            float4 v0 = *(const float4*)&g_s2t[j * B_];
            float4 v1 = *(const float4*)&g_s2t[j * B_ + 4];
            m[0] = fmaxf(m[0], v0.x); m[1] = fmaxf(m[1], v0.y);
            m[2] = fmaxf(m[2], v0.z); m[3] = fmaxf(m[3], v0.w);
            m[4] = fmaxf(m[4], v1.x); m[5] = fmaxf(m[5], v1.y);
            m[6] = fmaxf(m[6], v1.z); m[7] = fmaxf(m[7], v1.w);
        }
    }
    #pragma unroll
    for (int o = 16; o > 0; o >>= 1)
        #pragma unroll
        for (int bb = 0; bb < 8; bb++)
            m[bb] = fmaxf(m[bb], __shfl_xor_sync(0xffffffffu, m[bb], o));
    if (lane == 0) {
        #pragma unroll
        for (int bb = 0; bb < 8; bb++) g_m2[bb * N_ + i] = m[bb];
    }
}

// ---------------------------------------------------------------------------
// Kernel C: single-pass masked softmax aggregation (row max precomputed).
//   CTA = (64 i-rows, one batch); 32 j-tiles of 64; packed FFMA2 aggregation.
// ---------------------------------------------------------------------------
#define PJ 68                                    // P stride (float4-alignable)
#define SMEM_C ((64 * 128 + 64 * PJ + 4 * 64) * 4)

__global__ void __launch_bounds__(128) gat_attn(const int* __restrict__ adj,
                                                float* __restrict__ out) {
    extern __shared__ float sm[];
    float* Whs = sm;                             // [64][128]
    float* P   = sm + 64 * 128;                  // [64][PJ]
    float* s1s = P + 64 * PJ;                    // [64]
    float* s2s = s1s + 64;
    float* Ms  = s2s + 64;
    float* ls  = Ms + 64;

    const int tid = threadIdx.x;
    const int tx = tid & 15, ty = tid >> 4;
    const int b = blockIdx.y;
    const int i0 = blockIdx.x * 64;
    const float* WhB = g_Wh + b * N_ * F_;

    if (tid < 64) {
        float s1 = g_s1[b * N_ + i0 + tid];
        float m2 = g_m2[b * N_ + i0 + tid];
        s1s[tid] = s1;
        float Mi;
        if (m2 < -8.0e15f) {
            Mi = NEG_BIG;                        // empty row -> uniform softmax
        } else {
            float x = s1 + m2;
            Mi = fmaxf(x, ALPHA * x);            // lr monotone -> row max
        }
        Ms[tid] = Mi;
    }

    u64 acc[8][4];
    #pragma unroll
    for (int r = 0; r < 8; r++)
        #pragma unroll
        for (int c = 0; c < 4; c++) acc[r][c] = 0ULL;
    float lacc = 0.f;                            // valid on even tids (row tid>>1)

    const int jfix  = tid & 63;
    const int ibase = tid >> 6;

    for (int jt = 0; jt < N_ / 64; jt++) {
        const int j0 = jt * 64;
        #pragma unroll
        for (int p = 0; p < 16; p++) {
            int idx = tid + 128 * p;
            int r = idx >> 5;
            int c4 = idx & 31;
            *(float4*)&Whs[r * 128 + c4 * 4] =
                *(const float4*)&WhB[(j0 + r) * F_ + c4 * 4];
        }
        if (tid < 64) s2s[tid] = g_s2[b * N_ + j0 + tid];
        __syncthreads();

        // Scores + exp: p = exp(masked_leakyrelu(s1+s2) - M). 128 threads.
        {
            float s2v = s2s[jfix];
            const int* arow = adj + (long)(i0 + ibase) * N_ + j0 + jfix;
            #pragma unroll 8
            for (int k = 0; k < 32; k++) {
                int i = ibase + 2 * k;
                int ad = arow[2 * k * N_];
                float x = s1s[i] + s2v;
                float lr = fmaxf(x, ALPHA * x);
                float scv = (ad > 0) ? lr : NEG_BIG;
                P[i * PJ + jfix] = __expf(scv - Ms[i]);
            }
        }
        __syncthreads();

        // l partial sums: 2 threads per row, 32 entries each.
        {
            int row = tid >> 1, half = tid & 1;
            const float* Pr = &P[row * PJ + half * 32];
            float s = 0.f;
            #pragma unroll
            for (int c = 0; c < 32; c += 4) {
                float4 v = *(const float4*)&Pr[c];
                s += v.x + v.y + v.z + v.w;
            }
            float partner = __shfl_down_sync(0xffffffffu, s, 1);
            if (!(tid & 1)) lacc += s + partner;
        }

        // Aggregation: P(64x64) @ WhTile(64x128) with packed FFMA2.
        #pragma unroll 4
        for (int jj = 0; jj < 64; jj++) {
            u64 pp[8];
            #pragma unroll
            for (int r = 0; r < 8; r++) pp[r] = dup2(P[(ty * 8 + r) * PJ + jj]);
            ulonglong2 wa = *(ulonglong2*)&Whs[jj * 128 + tx * 8];
            ulonglong2 wb = *(ulonglong2*)&Whs[jj * 128 + tx * 8 + 4];
            #pragma unroll
            for (int r = 0; r < 8; r++) {
                acc[r][0] = ffma2(pp[r], wa.x, acc[r][0]);
                acc[r][1] = ffma2(pp[r], wa.y, acc[r][1]);
                acc[r][2] = ffma2(pp[r], wb.x, acc[r][2]);
                acc[r][3] = ffma2(pp[r], wb.y, acc[r][3]);
            }
        }
        __syncthreads();
    }

    if (!(tid & 1)) ls[tid >> 1] = lacc;
    __syncthreads();

    #pragma unroll
    for (int r = 0; r < 8; r++) {
        int i = ty * 8 + r;
        float inv = 1.f / ls[i];
        int row = b * N_ + i0 + i;
        float2 a0 = *(float2*)&acc[r][0];
        float2 a1 = *(float2*)&acc[r][1];
        float2 a2 = *(float2*)&acc[r][2];
        float2 a3 = *(float2*)&acc[r][3];
        float4 o0 = make_float4(a0.x * inv, a0.y * inv, a1.x * inv, a1.y * inv);
        float4 o1 = make_float4(a2.x * inv, a2.y * inv, a3.x * inv, a3.y * inv);
        *(float4*)&out[row * F_ + tx * 8] = o0;
        *(float4*)&out[row * F_ + tx * 8 + 4] = o1;
    }
}

// ---------------------------------------------------------------------------
extern "C" void kernel_launch(void* const* d_in, const int* in_sizes, int n_in,
                              void* d_out, int out_size) {
    const float* h   = (const float*)d_in[0];   // [8,2048,128]
    const int*   adj = (const int*)d_in[1];     // [2048,2048]
    const float* W   = (const float*)d_in[2];   // [128,128]
    const float* a   = (const float*)d_in[3];   // [256,1]
    float* out = (float*)d_out;                 // [8,2048,128]

    (void)in_sizes; (void)n_in; (void)out_size;

    static bool attr_set = false;
    if (!attr_set) {
        cudaFuncSetAttribute(gat_attn,
                             cudaFuncAttributeMaxDynamicSharedMemorySize,
                             SMEM_C);
        attr_set = true;
    }

    wh_gemm<<<(B_ * N_) / 64, 128>>>(h, W);
    compute_s<<<(B_ * N_) / 8, 256>>>(a);
    row_max<<<N_ / 8, 256>>>(adj);
    gat_attn<<<dim3(N_ / 64, B_), 128, SMEM_C>>>(adj, out);
}

// round 5
// speedup vs baseline: 1.2638x; 1.2638x over previous
#include <cuda_runtime.h>

#define ALPHA   0.2f
#define NEG_BIG -9.0e15f

#define B_   8
#define N_   2048
#define F_   128
#define S_   4            // j-splits per (batch, i-tile)

// Scratch (device globals — no allocation allowed in kernel_launch)
__device__ float g_Wh[B_ * N_ * F_];            // 8 MB
__device__ float g_s1[B_ * N_];
__device__ float g_s2[B_ * N_];
__device__ float g_s2t[N_ * B_];                // transposed s2: [j][b]
__device__ float g_m2[B_ * N_];                 // masked row-max of s2
__device__ float g_pacc[S_ * B_ * N_ * F_];     // partial aggregates, 32 MB
__device__ float g_pl[S_ * B_ * N_];            // partial l sums

typedef unsigned long long u64;

// Packed fp32x2 FMA (sm_103a FFMA2): d = a*b + c element-wise.
__device__ __forceinline__ u64 ffma2(u64 a, u64 b, u64 c) {
    u64 d;
    asm("fma.rn.f32x2 %0, %1, %2, %3;" : "=l"(d) : "l"(a), "l"(b), "l"(c));
    return d;
}
__device__ __forceinline__ u64 dup2(float x) {
    u64 d;
    unsigned int xi = __float_as_uint(x);
    asm("mov.b64 %0, {%1, %2};" : "=l"(d) : "r"(xi), "r"(xi));
    return d;
}

// ---------------------------------------------------------------------------
// Kernel A: Wh = h @ W with packed FFMA2.
// ---------------------------------------------------------------------------
__global__ void __launch_bounds__(128) wh_gemm(const float* __restrict__ h,
                                               const float* __restrict__ W) {
    __shared__ float hs[64][32];
    __shared__ float Ws[32][128];
    const int tid = threadIdx.x;
    const int tx = tid & 15, ty = tid >> 4;
    const int i0 = blockIdx.x * 64;

    u64 acc[8][4];
    #pragma unroll
    for (int r = 0; r < 8; r++)
        #pragma unroll
        for (int c = 0; c < 4; c++) acc[r][c] = 0ULL;

    for (int k0 = 0; k0 < F_; k0 += 32) {
        #pragma unroll
        for (int p = 0; p < 4; p++) {
            int idx = tid + 128 * p;
            int r = idx >> 3;
            int c4 = idx & 7;
            *(float4*)&hs[r][c4 * 4] =
                *(const float4*)&h[(i0 + r) * F_ + k0 + c4 * 4];
        }
        #pragma unroll
        for (int p = 0; p < 8; p++) {
            int idx = tid + 128 * p;
            int r = idx >> 5;
            int c4 = idx & 31;
            *(float4*)&Ws[r][c4 * 4] =
                *(const float4*)&W[(k0 + r) * F_ + c4 * 4];
        }
        __syncthreads();
        #pragma unroll
        for (int kk = 0; kk < 32; kk++) {
            u64 av[8];
            #pragma unroll
            for (int r = 0; r < 8; r++) av[r] = dup2(hs[ty * 8 + r][kk]);
            ulonglong2 wa = *(ulonglong2*)&Ws[kk][tx * 8];
            ulonglong2 wb = *(ulonglong2*)&Ws[kk][tx * 8 + 4];
            #pragma unroll
            for (int r = 0; r < 8; r++) {
                acc[r][0] = ffma2(av[r], wa.x, acc[r][0]);
                acc[r][1] = ffma2(av[r], wa.y, acc[r][1]);
                acc[r][2] = ffma2(av[r], wb.x, acc[r][2]);
                acc[r][3] = ffma2(av[r], wb.y, acc[r][3]);
            }
        }
        __syncthreads();
    }
    #pragma unroll
    for (int r = 0; r < 8; r++) {
        int row = i0 + ty * 8 + r;
        ulonglong2 o0, o1;
        o0.x = acc[r][0]; o0.y = acc[r][1];
        o1.x = acc[r][2]; o1.y = acc[r][3];
        *(ulonglong2*)&g_Wh[row * F_ + tx * 8] = o0;
        *(ulonglong2*)&g_Wh[row * F_ + tx * 8 + 4] = o1;
    }
}

// ---------------------------------------------------------------------------
// Kernel B: s1/s2 = Wh·a1 / Wh·a2, plus transposed s2t[j][b].
// ---------------------------------------------------------------------------
__global__ void __launch_bounds__(256) compute_s(const float* __restrict__ a) {
    int row = blockIdx.x * 8 + (threadIdx.x >> 5);
    int lane = threadIdx.x & 31;
    float4 w  = *(const float4*)&g_Wh[row * F_ + lane * 4];
    float4 a1 = *(const float4*)&a[lane * 4];
    float4 a2 = *(const float4*)&a[F_ + lane * 4];
    float d1 = w.x * a1.x + w.y * a1.y + w.z * a1.z + w.w * a1.w;
    float d2 = w.x * a2.x + w.y * a2.y + w.z * a2.z + w.w * a2.w;
    #pragma unroll
    for (int o = 16; o > 0; o >>= 1) {
        d1 += __shfl_xor_sync(0xffffffffu, d1, o);
        d2 += __shfl_xor_sync(0xffffffffu, d2, o);
    }
    if (lane == 0) {
        g_s1[row] = d1;
        g_s2[row] = d2;
        int b = row >> 11;          // N_ = 2048
        int i = row & (N_ - 1);
        g_s2t[i * B_ + b] = d2;
    }
}

// ---------------------------------------------------------------------------
// Kernel B2: m2[b][i] = max over j with adj[i,j]>0 of s2[b][j].
// ---------------------------------------------------------------------------
__global__ void __launch_bounds__(256) row_max(const int* __restrict__ adj) {
    int i = blockIdx.x * 8 + (threadIdx.x >> 5);
    int lane = threadIdx.x & 31;
    float m[8];
    #pragma unroll
    for (int bb = 0; bb < 8; bb++) m[bb] = NEG_BIG;

    #pragma unroll 4
    for (int it = 0; it < N_ / 32; it++) {
        int j = it * 32 + lane;
        int ad = adj[i * N_ + j];
        if (ad > 0) {
            float4 v0 = *(const float4*)&g_s2t[j * B_];
            float4 v1 = *(const float4*)&g_s2t[j * B_ + 4];
            m[0] = fmaxf(m[0], v0.x); m[1] = fmaxf(m[1], v0.y);
            m[2] = fmaxf(m[2], v0.z); m[3] = fmaxf(m[3], v0.w);
            m[4] = fmaxf(m[4], v1.x); m[5] = fmaxf(m[5], v1.y);
            m[6] = fmaxf(m[6], v1.z); m[7] = fmaxf(m[7], v1.w);
        }
    }
    #pragma unroll
    for (int o = 16; o > 0; o >>= 1)
        #pragma unroll
        for (int bb = 0; bb < 8; bb++)
            m[bb] = fmaxf(m[bb], __shfl_xor_sync(0xffffffffu, m[bb], o));
    if (lane == 0) {
        #pragma unroll
        for (int bb = 0; bb < 8; bb++) g_m2[bb * N_ + i] = m[bb];
    }
}

// ---------------------------------------------------------------------------
// Kernel C: split-j masked softmax aggregation (global row max -> partials
// are exactly additive across splits). CTA = (64 i-rows, batch, split).
// Each CTA handles N_/S_ = 512 j-values (8 tiles of 64), writes unnormalized
// partial accumulator + partial l.
// ---------------------------------------------------------------------------
#define PJ 68                                    // P stride (float4-alignable)
#define SMEM_C ((64 * 128 + 64 * PJ + 3 * 64) * 4)

__global__ void __launch_bounds__(128, 4) gat_attn(const int* __restrict__ adj) {
    extern __shared__ float sm[];
    float* Whs = sm;                             // [64][128]
    float* P   = sm + 64 * 128;                  // [64][PJ]
    float* s1s = P + 64 * PJ;                    // [64]
    float* s2s = s1s + 64;
    float* Ms  = s2s + 64;

    const int tid = threadIdx.x;
    const int tx = tid & 15, ty = tid >> 4;
    const int b = blockIdx.y;
    const int s = blockIdx.z;
    const int i0 = blockIdx.x * 64;
    const float* WhB = g_Wh + b * N_ * F_;

    if (tid < 64) {
        float s1 = g_s1[b * N_ + i0 + tid];
        float m2 = g_m2[b * N_ + i0 + tid];
        s1s[tid] = s1;
        float Mi;
        if (m2 < -8.0e15f) {
            Mi = NEG_BIG;                        // empty row -> uniform softmax
        } else {
            float x = s1 + m2;
            Mi = fmaxf(x, ALPHA * x);            // lr monotone -> row max
        }
        Ms[tid] = Mi;
    }

    u64 acc[8][4];
    #pragma unroll
    for (int r = 0; r < 8; r++)
        #pragma unroll
        for (int c = 0; c < 4; c++) acc[r][c] = 0ULL;
    float lacc = 0.f;                            // valid on even tids (row tid>>1)

    const int jfix  = tid & 63;
    const int ibase = tid >> 6;

    const int jt0 = s * (N_ / 64 / S_);          // 8 tiles per split
    const int jt1 = jt0 + (N_ / 64 / S_);

    for (int jt = jt0; jt < jt1; jt++) {
        const int j0 = jt * 64;
        #pragma unroll
        for (int p = 0; p < 16; p++) {
            int idx = tid + 128 * p;
            int r = idx >> 5;
            int c4 = idx & 31;
            *(float4*)&Whs[r * 128 + c4 * 4] =
                *(const float4*)&WhB[(j0 + r) * F_ + c4 * 4];
        }
        if (tid < 64) s2s[tid] = g_s2[b * N_ + j0 + tid];
        __syncthreads();

        // Scores + exp: p = exp(masked_leakyrelu(s1+s2) - M). 128 threads.
        {
            float s2v = s2s[jfix];
            const int* arow = adj + (long)(i0 + ibase) * N_ + j0 + jfix;
            #pragma unroll 8
            for (int k = 0; k < 32; k++) {
                int i = ibase + 2 * k;
                int ad = arow[2 * k * N_];
                float x = s1s[i] + s2v;
                float lr = fmaxf(x, ALPHA * x);
                float scv = (ad > 0) ? lr : NEG_BIG;
                P[i * PJ + jfix] = __expf(scv - Ms[i]);
            }
        }
        __syncthreads();

        // l partial sums: 2 threads per row, 32 entries each.
        {
            int row = tid >> 1, half = tid & 1;
            const float* Pr = &P[row * PJ + half * 32];
            float sum = 0.f;
            #pragma unroll
            for (int c = 0; c < 32; c += 4) {
                float4 v = *(const float4*)&Pr[c];
                sum += v.x + v.y + v.z + v.w;
            }
            float partner = __shfl_down_sync(0xffffffffu, sum, 1);
            if (!(tid & 1)) lacc += sum + partner;
        }

        // Aggregation: P(64x64) @ WhTile(64x128), packed FFMA2, float2 P loads.
        #pragma unroll 2
        for (int jj = 0; jj < 64; jj += 2) {
            float2 p2[8];
            #pragma unroll
            for (int r = 0; r < 8; r++)
                p2[r] = *(const float2*)&P[(ty * 8 + r) * PJ + jj];
            #pragma unroll
            for (int q = 0; q < 2; q++) {
                const float* wrow = &Whs[(jj + q) * 128 + tx * 8];
                ulonglong2 wa = *(const ulonglong2*)wrow;
                ulonglong2 wb = *(const ulonglong2*)(wrow + 4);
                #pragma unroll
                for (int r = 0; r < 8; r++) {
                    u64 pp = dup2(q ? p2[r].y : p2[r].x);
                    acc[r][0] = ffma2(pp, wa.x, acc[r][0]);
                    acc[r][1] = ffma2(pp, wa.y, acc[r][1]);
                    acc[r][2] = ffma2(pp, wb.x, acc[r][2]);
                    acc[r][3] = ffma2(pp, wb.y, acc[r][3]);
                }
            }
        }
        __syncthreads();
    }

    // Write partial l and partial accumulator (unnormalized).
    if (!(tid & 1)) g_pl[(s * B_ + b) * N_ + i0 + (tid >> 1)] = lacc;

    float* pout = g_pacc + ((long)(s * B_ + b) * N_ + i0) * F_;
    #pragma unroll
    for (int r = 0; r < 8; r++) {
        int i = ty * 8 + r;
        ulonglong2 o0, o1;
        o0.x = acc[r][0]; o0.y = acc[r][1];
        o1.x = acc[r][2]; o1.y = acc[r][3];
        *(ulonglong2*)&pout[i * F_ + tx * 8] = o0;
        *(ulonglong2*)&pout[i * F_ + tx * 8 + 4] = o1;
    }
}

// ---------------------------------------------------------------------------
// Kernel D: reduce splits. out[b,i,f] = sum_s pacc / sum_s pl.
// One float4 per thread.
// ---------------------------------------------------------------------------
__global__ void __launch_bounds__(256) reduce_splits(float* __restrict__ out) {
    const long idx = (long)blockIdx.x * 256 + threadIdx.x;   // float4 index
    const long row = idx >> 5;                               // F_/4 = 32 per row
    const long NBF = (long)B_ * N_ * F_ / 4;                 // float4 per split

    float l = 0.f;
    #pragma unroll
    for (int s = 0; s < S_; s++) l += g_pl[s * B_ * N_ + row];
    float inv = 1.f / l;

    float4 acc = make_float4(0.f, 0.f, 0.f, 0.f);
    const float4* pa = (const float4*)g_pacc;
    #pragma unroll
    for (int s = 0; s < S_; s++) {
        float4 v = pa[s * NBF + idx];
        acc.x += v.x; acc.y += v.y; acc.z += v.z; acc.w += v.w;
    }
    float4 o = make_float4(acc.x * inv, acc.y * inv, acc.z * inv, acc.w * inv);
    ((float4*)out)[idx] = o;
}

// ---------------------------------------------------------------------------
extern "C" void kernel_launch(void* const* d_in, const int* in_sizes, int n_in,
                              void* d_out, int out_size) {
    const float* h   = (const float*)d_in[0];   // [8,2048,128]
    const int*   adj = (const int*)d_in[1];     // [2048,2048]
    const float* W   = (const float*)d_in[2];   // [128,128]
    const float* a   = (const float*)d_in[3];   // [256,1]
    float* out = (float*)d_out;                 // [8,2048,128]

    (void)in_sizes; (void)n_in; (void)out_size;

    static bool attr_set = false;
    if (!attr_set) {
        cudaFuncSetAttribute(gat_attn,
                             cudaFuncAttributeMaxDynamicSharedMemorySize,
                             SMEM_C);
        attr_set = true;
    }

    wh_gemm<<<(B_ * N_) / 64, 128>>>(h, W);
    compute_s<<<(B_ * N_) / 8, 256>>>(a);
    row_max<<<N_ / 8, 256>>>(adj);
    gat_attn<<<dim3(N_ / 64, B_, S_), 128, SMEM_C>>>(adj);
    reduce_splits<<<(B_ * N_ * F_ / 4) / 256, 256>>>(out);
}

// round 6
// speedup vs baseline: 1.3964x; 1.1049x over previous
#include <cuda_runtime.h>

#define ALPHA   0.2f
#define NEG_BIG -9.0e15f

#define B_   8
#define N_   2048
#define F_   128
#define S_   4            // j-splits per (batch, i-tile)

// Scratch (device globals — no allocation allowed in kernel_launch)
__device__ float g_Wh[B_ * N_ * F_];            // 8 MB
__device__ float g_s1[B_ * N_];
__device__ float g_s2[B_ * N_];
__device__ float g_s2t[N_ * B_];                // transposed s2: [j][b]
__device__ float g_m2[B_ * N_];                 // masked row-max of s2
__device__ float g_pacc[S_ * B_ * N_ * F_];     // partial aggregates, 32 MB
__device__ float g_pl[S_ * B_ * N_];            // partial l sums

typedef unsigned long long u64;

// Packed fp32x2 FMA (sm_103a FFMA2): d = a*b + c element-wise.
__device__ __forceinline__ u64 ffma2(u64 a, u64 b, u64 c) {
    u64 d;
    asm("fma.rn.f32x2 %0, %1, %2, %3;" : "=l"(d) : "l"(a), "l"(b), "l"(c));
    return d;
}
__device__ __forceinline__ u64 dup2(float x) {
    u64 d;
    unsigned int xi = __float_as_uint(x);
    asm("mov.b64 %0, {%1, %2};" : "=l"(d) : "r"(xi), "r"(xi));
    return d;
}

// ---------------------------------------------------------------------------
// Kernel A: Wh = h @ W with packed FFMA2.
// ---------------------------------------------------------------------------
__global__ void __launch_bounds__(128) wh_gemm(const float* __restrict__ h,
                                               const float* __restrict__ W) {
    __shared__ float hs[64][32];
    __shared__ float Ws[32][128];
    const int tid = threadIdx.x;
    const int tx = tid & 15, ty = tid >> 4;
    const int i0 = blockIdx.x * 64;

    u64 acc[8][4];
    #pragma unroll
    for (int r = 0; r < 8; r++)
        #pragma unroll
        for (int c = 0; c < 4; c++) acc[r][c] = 0ULL;

    for (int k0 = 0; k0 < F_; k0 += 32) {
        #pragma unroll
        for (int p = 0; p < 4; p++) {
            int idx = tid + 128 * p;
            int r = idx >> 3;
            int c4 = idx & 7;
            *(float4*)&hs[r][c4 * 4] =
                *(const float4*)&h[(i0 + r) * F_ + k0 + c4 * 4];
        }
        #pragma unroll
        for (int p = 0; p < 8; p++) {
            int idx = tid + 128 * p;
            int r = idx >> 5;
            int c4 = idx & 31;
            *(float4*)&Ws[r][c4 * 4] =
                *(const float4*)&W[(k0 + r) * F_ + c4 * 4];
        }
        __syncthreads();
        #pragma unroll
        for (int kk = 0; kk < 32; kk++) {
            u64 av[8];
            #pragma unroll
            for (int r = 0; r < 8; r++) av[r] = dup2(hs[ty * 8 + r][kk]);
            ulonglong2 wa = *(ulonglong2*)&Ws[kk][tx * 8];
            ulonglong2 wb = *(ulonglong2*)&Ws[kk][tx * 8 + 4];
            #pragma unroll
            for (int r = 0; r < 8; r++) {
                acc[r][0] = ffma2(av[r], wa.x, acc[r][0]);
                acc[r][1] = ffma2(av[r], wa.y, acc[r][1]);
                acc[r][2] = ffma2(av[r], wb.x, acc[r][2]);
                acc[r][3] = ffma2(av[r], wb.y, acc[r][3]);
            }
        }
        __syncthreads();
    }
    #pragma unroll
    for (int r = 0; r < 8; r++) {
        int row = i0 + ty * 8 + r;
        ulonglong2 o0, o1;
        o0.x = acc[r][0]; o0.y = acc[r][1];
        o1.x = acc[r][2]; o1.y = acc[r][3];
        *(ulonglong2*)&g_Wh[row * F_ + tx * 8] = o0;
        *(ulonglong2*)&g_Wh[row * F_ + tx * 8 + 4] = o1;
    }
}

// ---------------------------------------------------------------------------
// Kernel B: s1/s2 = Wh·a1 / Wh·a2, plus transposed s2t[j][b].
// ---------------------------------------------------------------------------
__global__ void __launch_bounds__(256) compute_s(const float* __restrict__ a) {
    int row = blockIdx.x * 8 + (threadIdx.x >> 5);
    int lane = threadIdx.x & 31;
    float4 w  = *(const float4*)&g_Wh[row * F_ + lane * 4];
    float4 a1 = *(const float4*)&a[lane * 4];
    float4 a2 = *(const float4*)&a[F_ + lane * 4];
    float d1 = w.x * a1.x + w.y * a1.y + w.z * a1.z + w.w * a1.w;
    float d2 = w.x * a2.x + w.y * a2.y + w.z * a2.z + w.w * a2.w;
    #pragma unroll
    for (int o = 16; o > 0; o >>= 1) {
        d1 += __shfl_xor_sync(0xffffffffu, d1, o);
        d2 += __shfl_xor_sync(0xffffffffu, d2, o);
    }
    if (lane == 0) {
        g_s1[row] = d1;
        g_s2[row] = d2;
        int b = row >> 11;          // N_ = 2048
        int i = row & (N_ - 1);
        g_s2t[i * B_ + b] = d2;
    }
}

// ---------------------------------------------------------------------------
// Kernel B2: m2[b][i] = max over j with adj[i,j]>0 of s2[b][j].
// ---------------------------------------------------------------------------
__global__ void __launch_bounds__(256) row_max(const int* __restrict__ adj) {
    int i = blockIdx.x * 8 + (threadIdx.x >> 5);
    int lane = threadIdx.x & 31;
    float m[8];
    #pragma unroll
    for (int bb = 0; bb < 8; bb++) m[bb] = NEG_BIG;

    #pragma unroll 4
    for (int it = 0; it < N_ / 32; it++) {
        int j = it * 32 + lane;
        int ad = adj[i * N_ + j];
        if (ad > 0) {
            float4 v0 = *(const float4*)&g_s2t[j * B_];
            float4 v1 = *(const float4*)&g_s2t[j * B_ + 4];
            m[0] = fmaxf(m[0], v0.x); m[1] = fmaxf(m[1], v0.y);
            m[2] = fmaxf(m[2], v0.z); m[3] = fmaxf(m[3], v0.w);
            m[4] = fmaxf(m[4], v1.x); m[5] = fmaxf(m[5], v1.y);
            m[6] = fmaxf(m[6], v1.z); m[7] = fmaxf(m[7], v1.w);
        }
    }
    #pragma unroll
    for (int o = 16; o > 0; o >>= 1)
        #pragma unroll
        for (int bb = 0; bb < 8; bb++)
            m[bb] = fmaxf(m[bb], __shfl_xor_sync(0xffffffffu, m[bb], o));
    if (lane == 0) {
        #pragma unroll
        for (int bb = 0; bb < 8; bb++) g_m2[bb * N_ + i] = m[bb];
    }
}

// ---------------------------------------------------------------------------
// Kernel C: split-j masked softmax aggregation. Global row max -> partials
// additive across splits. CTA = (64 i-rows, batch, split); 8 j-tiles of 64.
// ---------------------------------------------------------------------------
#define PJ 68                                    // P stride (float4-alignable)
#define SMEM_C ((64 * 128 + 64 * PJ + 3 * 64) * 4)

__global__ void __launch_bounds__(128, 4) gat_attn(const int* __restrict__ adj) {
    extern __shared__ float sm[];
    float* Whs = sm;                             // [64][128]
    float* P   = sm + 64 * 128;                  // [64][PJ]
    float* s1s = P + 64 * PJ;                    // [64]
    float* s2s = s1s + 64;
    float* Ms  = s2s + 64;

    const int tid = threadIdx.x;
    const int tx = tid & 15, ty = tid >> 4;
    const int b = blockIdx.y;
    const int s = blockIdx.z;
    const int i0 = blockIdx.x * 64;
    const float* WhB = g_Wh + b * N_ * F_;

    if (tid < 64) {
        float s1 = g_s1[b * N_ + i0 + tid];
        float m2 = g_m2[b * N_ + i0 + tid];
        s1s[tid] = s1;
        float Mi;
        if (m2 < -8.0e15f) {
            Mi = NEG_BIG;                        // empty row -> uniform softmax
        } else {
            float x = s1 + m2;
            Mi = fmaxf(x, ALPHA * x);            // lr monotone -> row max
        }
        Ms[tid] = Mi;
    }

    u64 acc[8][4];
    #pragma unroll
    for (int r = 0; r < 8; r++)
        #pragma unroll
        for (int c = 0; c < 4; c++) acc[r][c] = 0ULL;
    float lacc = 0.f;                            // valid on even tids (row tid>>1)

    const int jt0 = s * (N_ / 64 / S_);          // 8 tiles per split
    const int jt1 = jt0 + (N_ / 64 / S_);

    for (int jt = jt0; jt < jt1; jt++) {
        const int j0 = jt * 64;
        #pragma unroll
        for (int p = 0; p < 16; p++) {
            int idx = tid + 128 * p;
            int r = idx >> 5;
            int c4 = idx & 31;
            *(float4*)&Whs[r * 128 + c4 * 4] =
                *(const float4*)&WhB[(j0 + r) * F_ + c4 * 4];
        }
        if (tid < 64) s2s[tid] = g_s2[b * N_ + j0 + tid];
        __syncthreads();

        // Scores + exp, 4-wide: quad q = tid + 128k -> (i = q>>4, j = 4*(q&15)).
        // Warp covers 2 rows x 256B of adj per instruction (coalesced int4).
        #pragma unroll
        for (int k = 0; k < 8; k++) {
            int q = tid + 128 * k;
            int i = q >> 4;
            int j = (q & 15) * 4;
            int4 ad = *(const int4*)&adj[(long)(i0 + i) * N_ + j0 + j];
            float s1v = s1s[i];
            float Mi  = Ms[i];
            float4 s2v = *(const float4*)&s2s[j];
            float4 pv;
            {
                float x0 = s1v + s2v.x, x1 = s1v + s2v.y;
                float x2 = s1v + s2v.z, x3 = s1v + s2v.w;
                float l0 = fmaxf(x0, ALPHA * x0), l1 = fmaxf(x1, ALPHA * x1);
                float l2 = fmaxf(x2, ALPHA * x2), l3 = fmaxf(x3, ALPHA * x3);
                pv.x = __expf(((ad.x > 0) ? l0 : NEG_BIG) - Mi);
                pv.y = __expf(((ad.y > 0) ? l1 : NEG_BIG) - Mi);
                pv.z = __expf(((ad.z > 0) ? l2 : NEG_BIG) - Mi);
                pv.w = __expf(((ad.w > 0) ? l3 : NEG_BIG) - Mi);
            }
            *(float4*)&P[i * PJ + j] = pv;
        }
        __syncthreads();

        // l partial sums: 2 threads per row, 32 entries each.
        {
            int row = tid >> 1, half = tid & 1;
            const float* Pr = &P[row * PJ + half * 32];
            float sum = 0.f;
            #pragma unroll
            for (int c = 0; c < 32; c += 4) {
                float4 v = *(const float4*)&Pr[c];
                sum += v.x + v.y + v.z + v.w;
            }
            float partner = __shfl_down_sync(0xffffffffu, sum, 1);
            if (!(tid & 1)) lacc += sum + partner;
        }

        // Aggregation: P(64x64) @ WhTile(64x128), FFMA2, float4 P loads.
        const float* Prow = P + ty * 8 * PJ;
        #pragma unroll 4
        for (int jj4 = 0; jj4 < 16; jj4++) {
            float4 p4[8];
            #pragma unroll
            for (int r = 0; r < 8; r++)
                p4[r] = *(const float4*)&Prow[r * PJ + jj4 * 4];
            #pragma unroll
            for (int qq = 0; qq < 4; qq++) {
                const float* wrow = &Whs[(jj4 * 4 + qq) * 128 + tx * 8];
                ulonglong2 wa = *(const ulonglong2*)wrow;
                ulonglong2 wb = *(const ulonglong2*)(wrow + 4);
                #pragma unroll
                for (int r = 0; r < 8; r++) {
                    float pvv = (qq == 0) ? p4[r].x :
                                (qq == 1) ? p4[r].y :
                                (qq == 2) ? p4[r].z : p4[r].w;
                    u64 pp = dup2(pvv);
                    acc[r][0] = ffma2(pp, wa.x, acc[r][0]);
                    acc[r][1] = ffma2(pp, wa.y, acc[r][1]);
                    acc[r][2] = ffma2(pp, wb.x, acc[r][2]);
                    acc[r][3] = ffma2(pp, wb.y, acc[r][3]);
                }
            }
        }
        __syncthreads();
    }

    // Write partial l and partial accumulator (unnormalized).
    if (!(tid & 1)) g_pl[(s * B_ + b) * N_ + i0 + (tid >> 1)] = lacc;

    float* pout = g_pacc + ((long)(s * B_ + b) * N_ + i0) * F_;
    #pragma unroll
    for (int r = 0; r < 8; r++) {
        int i = ty * 8 + r;
        ulonglong2 o0, o1;
        o0.x = acc[r][0]; o0.y = acc[r][1];
        o1.x = acc[r][2]; o1.y = acc[r][3];
        *(ulonglong2*)&pout[i * F_ + tx * 8] = o0;
        *(ulonglong2*)&pout[i * F_ + tx * 8 + 4] = o1;
    }
}

// ---------------------------------------------------------------------------
// Kernel D: reduce splits. out[b,i,f] = sum_s pacc / sum_s pl.
// ---------------------------------------------------------------------------
__global__ void __launch_bounds__(256) reduce_splits(float* __restrict__ out) {
    const long idx = (long)blockIdx.x * 256 + threadIdx.x;   // float4 index
    const long row = idx >> 5;                               // F_/4 = 32 per row
    const long NBF = (long)B_ * N_ * F_ / 4;                 // float4 per split

    float l = 0.f;
    #pragma unroll
    for (int s = 0; s < S_; s++) l += g_pl[s * B_ * N_ + row];
    float inv = 1.f / l;

    float4 acc = make_float4(0.f, 0.f, 0.f, 0.f);
    const float4* pa = (const float4*)g_pacc;
    #pragma unroll
    for (int s = 0; s < S_; s++) {
        float4 v = pa[s * NBF + idx];
        acc.x += v.x; acc.y += v.y; acc.z += v.z; acc.w += v.w;
    }
    float4 o = make_float4(acc.x * inv, acc.y * inv, acc.z * inv, acc.w * inv);
    ((float4*)out)[idx] = o;
}

// ---------------------------------------------------------------------------
extern "C" void kernel_launch(void* const* d_in, const int* in_sizes, int n_in,
                              void* d_out, int out_size) {
    const float* h   = (const float*)d_in[0];   // [8,2048,128]
    const int*   adj = (const int*)d_in[1];     // [2048,2048]
    const float* W   = (const float*)d_in[2];   // [128,128]
    const float* a   = (const float*)d_in[3];   // [256,1]
    float* out = (float*)d_out;                 // [8,2048,128]

    (void)in_sizes; (void)n_in; (void)out_size;

    static bool attr_set = false;
    if (!attr_set) {
        cudaFuncSetAttribute(gat_attn,
                             cudaFuncAttributeMaxDynamicSharedMemorySize,
                             SMEM_C);
        attr_set = true;
    }

    wh_gemm<<<(B_ * N_) / 64, 128>>>(h, W);
    compute_s<<<(B_ * N_) / 8, 256>>>(a);
    row_max<<<N_ / 8, 256>>>(adj);
    gat_attn<<<dim3(N_ / 64, B_, S_), 128, SMEM_C>>>(adj);
    reduce_splits<<<(B_ * N_ * F_ / 4) / 256, 256>>>(out);
}

// round 7
// speedup vs baseline: 1.5469x; 1.1078x over previous
#include <cuda_runtime.h>
#include <cuda_bf16.h>

#define ALPHA   0.2f
#define NEG_BIG -9.0e15f

#define B_   8
#define N_   2048
#define F_   128
#define S_   4            // j-splits per (batch, i-tile)

// Scratch (device globals — no allocation allowed in kernel_launch)
__device__ float g_Wh[B_ * N_ * F_];            // fp32, 8 MB (for compute_s)
__device__ __nv_bfloat16 g_Whh[B_ * N_ * F_];   // bf16 hi, 4 MB
__device__ __nv_bfloat16 g_Whl[B_ * N_ * F_];   // bf16 lo (residual), 4 MB
__device__ float g_s1[B_ * N_];
__device__ float g_s2[B_ * N_];
__device__ float g_s2t[N_ * B_];                // transposed s2: [j][b]
__device__ float g_m2[B_ * N_];                 // masked row-max of s2
__device__ float g_pacc[S_ * B_ * N_ * F_];     // partial aggregates, 32 MB
__device__ float g_pl[S_ * B_ * N_];            // partial l sums

typedef unsigned long long u64;
typedef unsigned int u32;

// Packed fp32x2 FMA (sm_103a FFMA2): d = a*b + c element-wise.
__device__ __forceinline__ u64 ffma2(u64 a, u64 b, u64 c) {
    u64 d;
    asm("fma.rn.f32x2 %0, %1, %2, %3;" : "=l"(d) : "l"(a), "l"(b), "l"(c));
    return d;
}
__device__ __forceinline__ u64 dup2(float x) {
    u64 d;
    u32 xi = __float_as_uint(x);
    asm("mov.b64 %0, {%1, %2};" : "=l"(d) : "r"(xi), "r"(xi));
    return d;
}

// ldmatrix x4 (non-transposed / transposed)
__device__ __forceinline__ void ldsm4(u32& r0, u32& r1, u32& r2, u32& r3, u32 a) {
    asm volatile("ldmatrix.sync.aligned.m8n8.x4.shared.b16 {%0,%1,%2,%3}, [%4];"
                 : "=r"(r0), "=r"(r1), "=r"(r2), "=r"(r3) : "r"(a));
}
__device__ __forceinline__ void ldsm4t(u32& r0, u32& r1, u32& r2, u32& r3, u32 a) {
    asm volatile("ldmatrix.sync.aligned.m8n8.x4.trans.shared.b16 {%0,%1,%2,%3}, [%4];"
                 : "=r"(r0), "=r"(r1), "=r"(r2), "=r"(r3) : "r"(a));
}

// mma.sync m16n8k16 bf16 -> fp32, D += A*B
__device__ __forceinline__ void mma16816(float* d, u32 a0, u32 a1, u32 a2, u32 a3,
                                         u32 b0, u32 b1) {
    asm volatile(
        "mma.sync.aligned.m16n8k16.row.col.f32.bf16.bf16.f32 "
        "{%0,%1,%2,%3}, {%4,%5,%6,%7}, {%8,%9}, {%0,%1,%2,%3};"
        : "+f"(d[0]), "+f"(d[1]), "+f"(d[2]), "+f"(d[3])
        : "r"(a0), "r"(a1), "r"(a2), "r"(a3), "r"(b0), "r"(b1));
}

// ---------------------------------------------------------------------------
// Kernel A: Wh = h @ W (FFMA2). Epilogue writes fp32 + bf16 hi/lo split.
// ---------------------------------------------------------------------------
__global__ void __launch_bounds__(128) wh_gemm(const float* __restrict__ h,
                                               const float* __restrict__ W) {
    __shared__ float hs[64][32];
    __shared__ float Ws[32][128];
    const int tid = threadIdx.x;
    const int tx = tid & 15, ty = tid >> 4;
    const int i0 = blockIdx.x * 64;

    u64 acc[8][4];
    #pragma unroll
    for (int r = 0; r < 8; r++)
        #pragma unroll
        for (int c = 0; c < 4; c++) acc[r][c] = 0ULL;

    for (int k0 = 0; k0 < F_; k0 += 32) {
        #pragma unroll
        for (int p = 0; p < 4; p++) {
            int idx = tid + 128 * p;
            int r = idx >> 3;
            int c4 = idx & 7;
            *(float4*)&hs[r][c4 * 4] =
                *(const float4*)&h[(i0 + r) * F_ + k0 + c4 * 4];
        }
        #pragma unroll
        for (int p = 0; p < 8; p++) {
            int idx = tid + 128 * p;
            int r = idx >> 5;
            int c4 = idx & 31;
            *(float4*)&Ws[r][c4 * 4] =
                *(const float4*)&W[(k0 + r) * F_ + c4 * 4];
        }
        __syncthreads();
        #pragma unroll
        for (int kk = 0; kk < 32; kk++) {
            u64 av[8];
            #pragma unroll
            for (int r = 0; r < 8; r++) av[r] = dup2(hs[ty * 8 + r][kk]);
            ulonglong2 wa = *(ulonglong2*)&Ws[kk][tx * 8];
            ulonglong2 wb = *(ulonglong2*)&Ws[kk][tx * 8 + 4];
            #pragma unroll
            for (int r = 0; r < 8; r++) {
                acc[r][0] = ffma2(av[r], wa.x, acc[r][0]);
                acc[r][1] = ffma2(av[r], wa.y, acc[r][1]);
                acc[r][2] = ffma2(av[r], wb.x, acc[r][2]);
                acc[r][3] = ffma2(av[r], wb.y, acc[r][3]);
            }
        }
        __syncthreads();
    }
    #pragma unroll
    for (int r = 0; r < 8; r++) {
        int row = i0 + ty * 8 + r;
        float v[8];
        #pragma unroll
        for (int c = 0; c < 4; c++) {
            float2 f = *(float2*)&acc[r][c];
            v[2 * c] = f.x; v[2 * c + 1] = f.y;
        }
        // fp32
        *(float4*)&g_Wh[row * F_ + tx * 8]     = make_float4(v[0], v[1], v[2], v[3]);
        *(float4*)&g_Wh[row * F_ + tx * 8 + 4] = make_float4(v[4], v[5], v[6], v[7]);
        // bf16 hi/lo split
        __nv_bfloat162 H[4], L[4];
        #pragma unroll
        for (int c = 0; c < 4; c++) {
            float x = v[2 * c], y = v[2 * c + 1];
            H[c] = __float22bfloat162_rn(make_float2(x, y));
            float lx = x - __low2float(H[c]);
            float ly = y - __high2float(H[c]);
            L[c] = __float22bfloat162_rn(make_float2(lx, ly));
        }
        uint4 uh, ul;
        uh.x = *(u32*)&H[0]; uh.y = *(u32*)&H[1]; uh.z = *(u32*)&H[2]; uh.w = *(u32*)&H[3];
        ul.x = *(u32*)&L[0]; ul.y = *(u32*)&L[1]; ul.z = *(u32*)&L[2]; ul.w = *(u32*)&L[3];
        *(uint4*)&g_Whh[row * F_ + tx * 8] = uh;
        *(uint4*)&g_Whl[row * F_ + tx * 8] = ul;
    }
}

// ---------------------------------------------------------------------------
// Kernel B: s1/s2 = Wh·a1 / Wh·a2, plus transposed s2t[j][b].
// ---------------------------------------------------------------------------
__global__ void __launch_bounds__(256) compute_s(const float* __restrict__ a) {
    int row = blockIdx.x * 8 + (threadIdx.x >> 5);
    int lane = threadIdx.x & 31;
    float4 w  = *(const float4*)&g_Wh[row * F_ + lane * 4];
    float4 a1 = *(const float4*)&a[lane * 4];
    float4 a2 = *(const float4*)&a[F_ + lane * 4];
    float d1 = w.x * a1.x + w.y * a1.y + w.z * a1.z + w.w * a1.w;
    float d2 = w.x * a2.x + w.y * a2.y + w.z * a2.z + w.w * a2.w;
    #pragma unroll
    for (int o = 16; o > 0; o >>= 1) {
        d1 += __shfl_xor_sync(0xffffffffu, d1, o);
        d2 += __shfl_xor_sync(0xffffffffu, d2, o);
    }
    if (lane == 0) {
        g_s1[row] = d1;
        g_s2[row] = d2;
        int b = row >> 11;          // N_ = 2048
        int i = row & (N_ - 1);
        g_s2t[i * B_ + b] = d2;
    }
}

// ---------------------------------------------------------------------------
// Kernel B2: m2[b][i] = max over j with adj[i,j]>0 of s2[b][j].
// ---------------------------------------------------------------------------
__global__ void __launch_bounds__(256) row_max(const int* __restrict__ adj) {
    int i = blockIdx.x * 8 + (threadIdx.x >> 5);
    int lane = threadIdx.x & 31;
    float m[8];
    #pragma unroll
    for (int bb = 0; bb < 8; bb++) m[bb] = NEG_BIG;

    #pragma unroll 4
    for (int it = 0; it < N_ / 32; it++) {
        int j = it * 32 + lane;
        int ad = adj[i * N_ + j];
        if (ad > 0) {
            float4 v0 = *(const float4*)&g_s2t[j * B_];
            float4 v1 = *(const float4*)&g_s2t[j * B_ + 4];
            m[0] = fmaxf(m[0], v0.x); m[1] = fmaxf(m[1], v0.y);
            m[2] = fmaxf(m[2], v0.z); m[3] = fmaxf(m[3], v0.w);
            m[4] = fmaxf(m[4], v1.x); m[5] = fmaxf(m[5], v1.y);
            m[6] = fmaxf(m[6], v1.z); m[7] = fmaxf(m[7], v1.w);
        }
    }
    #pragma unroll
    for (int o = 16; o > 0; o >>= 1)
        #pragma unroll
        for (int bb = 0; bb < 8; bb++)
            m[bb] = fmaxf(m[bb], __shfl_xor_sync(0xffffffffu, m[bb], o));
    if (lane == 0) {
        #pragma unroll
        for (int bb = 0; bb < 8; bb++) g_m2[bb * N_ + i] = m[bb];
    }
}

// ---------------------------------------------------------------------------
// Kernel C: split-j masked softmax aggregation with mma.sync bf16x3 tensor
// cores. CTA = (64 i-rows, batch, split); 8 j-tiles of 64.
//
// smem layout (bytes), strides padded for conflict-free ldmatrix
// (row-start bank = 4*r -> 8 rows x 16B cover all 32 banks):
//   WThi [64][136 bf16] stride 272B  @ 0      (17408)
//   WTlo                              @ 17408 (17408)
//   Phi  [64][72 bf16]  stride 144B  @ 34816 (9216)
//   Plo                               @ 44032 (9216)
//   s1s/s2s/Ms fp32[64]               @ 53248/53504/53760
// ---------------------------------------------------------------------------
#define OFF_WTHI 0
#define OFF_WTLO 17408
#define OFF_PHI  34816
#define OFF_PLO  44032
#define OFF_S1   53248
#define OFF_S2   53504
#define OFF_MS   53760
#define SMEM_C   54016

__global__ void __launch_bounds__(128, 4) gat_attn(const int* __restrict__ adj) {
    extern __shared__ char smc[];
    float* s1s = (float*)(smc + OFF_S1);
    float* s2s = (float*)(smc + OFF_S2);
    float* Ms  = (float*)(smc + OFF_MS);

    const int tid = threadIdx.x;
    const int lane = tid & 31;
    const int w = tid >> 5;                      // warp 0..3
    const int b = blockIdx.y;
    const int s = blockIdx.z;
    const int i0 = blockIdx.x * 64;

    const u32 sbase = (u32)__cvta_generic_to_shared(smc);

    if (tid < 64) {
        float s1 = g_s1[b * N_ + i0 + tid];
        float m2 = g_m2[b * N_ + i0 + tid];
        s1s[tid] = s1;
        float Mi;
        if (m2 < -8.0e15f) {
            Mi = NEG_BIG;                        // empty row -> uniform softmax
        } else {
            float x = s1 + m2;
            Mi = fmaxf(x, ALPHA * x);            // lr monotone -> row max
        }
        Ms[tid] = Mi;
    }

    float acc[16][4];                            // warp: 16 rows x 128 cols
    #pragma unroll
    for (int n = 0; n < 16; n++)
        #pragma unroll
        for (int c = 0; c < 4; c++) acc[n][c] = 0.f;
    float lacc[8];                               // row-sum partials, row g+8k
    #pragma unroll
    for (int k = 0; k < 8; k++) lacc[k] = 0.f;

    const int g  = tid >> 4;                     // 0..7: score-phase row group
    const int jq = (tid & 15) * 4;               // score-phase j quad

    // ldmatrix lane-invariant offsets
    const int lg = lane >> 3, lr = lane & 7;
    const u32 aoff = (u32)(((lg & 1) * 8 + lr) * 144 + (lg >> 1) * 16);
    const u32 boff = (u32)(((lg & 1) * 8 + lr) * 272 + (lg >> 1) * 16);
    const int r0 = w << 4;                       // warp's 16 MMA rows

    const int jt0 = s * (N_ / 64 / S_);          // 8 tiles per split
    const int jt1 = jt0 + (N_ / 64 / S_);

    for (int jt = jt0; jt < jt1; jt++) {
        const int j0 = jt * 64;

        // ---- fill: WThi/WTlo tiles (bf16, straight copy) + s2s ----
        {
            const uint4* srcH = (const uint4*)&g_Whh[(b * N_ + j0) * F_];
            const uint4* srcL = (const uint4*)&g_Whl[(b * N_ + j0) * F_];
            #pragma unroll
            for (int p = 0; p < 8; p++) {
                int idx = tid + 128 * p;         // 1024 uint4 (64 rows x 16)
                int r = idx >> 4;
                int c16 = idx & 15;
                *(uint4*)(smc + OFF_WTHI + r * 272 + c16 * 16) = srcH[r * 16 + c16];
                *(uint4*)(smc + OFF_WTLO + r * 272 + c16 * 16) = srcL[r * 16 + c16];
            }
            if (tid < 64) s2s[tid] = g_s2[b * N_ + j0 + tid];
        }
        __syncthreads();

        // ---- scores + exp + bf16 hi/lo split + register l-sums ----
        {
            float4 s2v = *(const float4*)&s2s[jq];
            const int* arow = adj + (long)(i0 + g) * N_ + j0 + jq;
            #pragma unroll
            for (int k = 0; k < 8; k++) {
                int i = g + 8 * k;
                int4 ad = *(const int4*)&arow[8 * k * N_];
                float s1v = s1s[i];
                float Mi  = Ms[i];
                float x0 = s1v + s2v.x, x1 = s1v + s2v.y;
                float x2 = s1v + s2v.z, x3 = s1v + s2v.w;
                float l0 = fmaxf(x0, ALPHA * x0), l1 = fmaxf(x1, ALPHA * x1);
                float l2 = fmaxf(x2, ALPHA * x2), l3 = fmaxf(x3, ALPHA * x3);
                float p0 = __expf(((ad.x > 0) ? l0 : NEG_BIG) - Mi);
                float p1 = __expf(((ad.y > 0) ? l1 : NEG_BIG) - Mi);
                float p2 = __expf(((ad.z > 0) ? l2 : NEG_BIG) - Mi);
                float p3 = __expf(((ad.w > 0) ? l3 : NEG_BIG) - Mi);
                lacc[k] += (p0 + p1) + (p2 + p3);
                __nv_bfloat162 h01 = __float22bfloat162_rn(make_float2(p0, p1));
                __nv_bfloat162 h23 = __float22bfloat162_rn(make_float2(p2, p3));
                float q0 = p0 - __low2float(h01),  q1 = p1 - __high2float(h01);
                float q2 = p2 - __low2float(h23),  q3 = p3 - __high2float(h23);
                __nv_bfloat162 l01 = __float22bfloat162_rn(make_float2(q0, q1));
                __nv_bfloat162 l23 = __float22bfloat162_rn(make_float2(q2, q3));
                uint2 uh, ulv;
                uh.x = *(u32*)&h01; uh.y = *(u32*)&h23;
                ulv.x = *(u32*)&l01; ulv.y = *(u32*)&l23;
                *(uint2*)(smc + OFF_PHI + i * 144 + jq * 2) = uh;
                *(uint2*)(smc + OFF_PLO + i * 144 + jq * 2) = ulv;
            }
        }
        __syncthreads();

        // ---- aggregation: P(64x64) @ Wh(64x128) via mma.sync bf16x3 ----
        {
            const u32 abase = sbase + OFF_PHI + (u32)(r0 * 144) + aoff;
            #pragma unroll
            for (int ks = 0; ks < 4; ks++) {
                u32 ah0, ah1, ah2, ah3, al0, al1, al2, al3;
                u32 aA = abase + ks * 32;
                ldsm4(ah0, ah1, ah2, ah3, aA);
                ldsm4(al0, al1, al2, al3, aA + (OFF_PLO - OFF_PHI));
                u32 bbase = sbase + OFF_WTHI + (u32)(ks * 16 * 272) + boff;
                #pragma unroll
                for (int np = 0; np < 8; np++) {
                    u32 bh0, bh1, bh2, bh3, bl0, bl1, bl2, bl3;
                    u32 bb = bbase + np * 32;
                    ldsm4t(bh0, bh1, bh2, bh3, bb);
                    ldsm4t(bl0, bl1, bl2, bl3, bb + (OFF_WTLO - OFF_WTHI));
                    mma16816(acc[2 * np],     ah0, ah1, ah2, ah3, bh0, bh1);
                    mma16816(acc[2 * np],     ah0, ah1, ah2, ah3, bl0, bl1);
                    mma16816(acc[2 * np],     al0, al1, al2, al3, bh0, bh1);
                    mma16816(acc[2 * np + 1], ah0, ah1, ah2, ah3, bh2, bh3);
                    mma16816(acc[2 * np + 1], ah0, ah1, ah2, ah3, bl2, bl3);
                    mma16816(acc[2 * np + 1], al0, al1, al2, al3, bh2, bh3);
                }
            }
        }
        __syncthreads();
    }

    // ---- partial l: reduce lacc over the 16-lane row groups ----
    #pragma unroll
    for (int k = 0; k < 8; k++) {
        float v = lacc[k];
        v += __shfl_xor_sync(0xffffffffu, v, 1);
        v += __shfl_xor_sync(0xffffffffu, v, 2);
        v += __shfl_xor_sync(0xffffffffu, v, 4);
        v += __shfl_xor_sync(0xffffffffu, v, 8);
        if ((tid & 15) == 0)
            g_pl[(s * B_ + b) * N_ + i0 + g + 8 * k] = v;
    }

    // ---- partial accumulator (unnormalized) ----
    {
        float* pout = g_pacc + ((long)(s * B_ + b) * N_ + i0) * F_;
        const int rr = r0 + (lane >> 2);
        const int c0 = 2 * (lane & 3);
        #pragma unroll
        for (int n = 0; n < 16; n++) {
            *(float2*)&pout[rr * F_ + 8 * n + c0]       = make_float2(acc[n][0], acc[n][1]);
            *(float2*)&pout[(rr + 8) * F_ + 8 * n + c0] = make_float2(acc[n][2], acc[n][3]);
        }
    }
}

// ---------------------------------------------------------------------------
// Kernel D: reduce splits. out[b,i,f] = sum_s pacc / sum_s pl.
// ---------------------------------------------------------------------------
__global__ void __launch_bounds__(256) reduce_splits(float* __restrict__ out) {
    const long idx = (long)blockIdx.x * 256 + threadIdx.x;   // float4 index
    const long row = idx >> 5;                               // F_/4 = 32 per row
    const long NBF = (long)B_ * N_ * F_ / 4;                 // float4 per split

    float l = 0.f;
    #pragma unroll
    for (int s = 0; s < S_; s++) l += g_pl[s * B_ * N_ + row];
    float inv = 1.f / l;

    float4 acc = make_float4(0.f, 0.f, 0.f, 0.f);
    const float4* pa = (const float4*)g_pacc;
    #pragma unroll
    for (int s = 0; s < S_; s++) {
        float4 v = pa[s * NBF + idx];
        acc.x += v.x; acc.y += v.y; acc.z += v.z; acc.w += v.w;
    }
    float4 o = make_float4(acc.x * inv, acc.y * inv, acc.z * inv, acc.w * inv);
    ((float4*)out)[idx] = o;
}

// ---------------------------------------------------------------------------
extern "C" void kernel_launch(void* const* d_in, const int* in_sizes, int n_in,
                              void* d_out, int out_size) {
    const float* h   = (const float*)d_in[0];   // [8,2048,128]
    const int*   adj = (const int*)d_in[1];     // [2048,2048]
    const float* W   = (const float*)d_in[2];   // [128,128]
    const float* a   = (const float*)d_in[3];   // [256,1]
    float* out = (float*)d_out;                 // [8,2048,128]

    (void)in_sizes; (void)n_in; (void)out_size;

    static bool attr_set = false;
    if (!attr_set) {
        cudaFuncSetAttribute(gat_attn,
                             cudaFuncAttributeMaxDynamicSharedMemorySize,
                             SMEM_C);
        attr_set = true;
    }

    wh_gemm<<<(B_ * N_) / 64, 128>>>(h, W);
    compute_s<<<(B_ * N_) / 8, 256>>>(a);
    row_max<<<N_ / 8, 256>>>(adj);
    gat_attn<<<dim3(N_ / 64, B_, S_), 128, SMEM_C>>>(adj);
    reduce_splits<<<(B_ * N_ * F_ / 4) / 256, 256>>>(out);
}

// round 8
// speedup vs baseline: 2.3154x; 1.4967x over previous
#include <cuda_runtime.h>
#include <cuda_bf16.h>

#define ALPHA   0.2f
#define NEG_BIG -9.0e15f

#define B_   8
#define N_   2048
#define F_   128
#define S_   4            // j-splits per (batch, i-tile)

// Scratch (device globals — no allocation allowed in kernel_launch)
__device__ float g_Wh[B_ * N_ * F_];            // fp32, 8 MB (for compute_s)
__device__ __nv_bfloat16 g_Whh[B_ * N_ * F_];   // bf16 hi, 4 MB
__device__ __nv_bfloat16 g_Whl[B_ * N_ * F_];   // bf16 lo (residual), 4 MB
__device__ float g_s1[B_ * N_];
__device__ float g_s2[B_ * N_];
__device__ float g_s2t[N_ * B_];                // transposed s2: [j][b]
__device__ float g_m2[B_ * N_];                 // masked row-max of s2
__device__ float g_pacc[S_ * B_ * N_ * F_];     // partial aggregates, 32 MB
__device__ float g_pl[S_ * B_ * N_];            // partial l sums

typedef unsigned long long u64;
typedef unsigned int u32;

// Packed fp32x2 FMA (sm_103a FFMA2): d = a*b + c element-wise.
__device__ __forceinline__ u64 ffma2(u64 a, u64 b, u64 c) {
    u64 d;
    asm("fma.rn.f32x2 %0, %1, %2, %3;" : "=l"(d) : "l"(a), "l"(b), "l"(c));
    return d;
}
__device__ __forceinline__ u64 dup2(float x) {
    u64 d;
    u32 xi = __float_as_uint(x);
    asm("mov.b64 %0, {%1, %2};" : "=l"(d) : "r"(xi), "r"(xi));
    return d;
}

// ldmatrix x4 (non-transposed / transposed)
__device__ __forceinline__ void ldsm4(u32& r0, u32& r1, u32& r2, u32& r3, u32 a) {
    asm volatile("ldmatrix.sync.aligned.m8n8.x4.shared.b16 {%0,%1,%2,%3}, [%4];"
                 : "=r"(r0), "=r"(r1), "=r"(r2), "=r"(r3) : "r"(a));
}
__device__ __forceinline__ void ldsm4t(u32& r0, u32& r1, u32& r2, u32& r3, u32 a) {
    asm volatile("ldmatrix.sync.aligned.m8n8.x4.trans.shared.b16 {%0,%1,%2,%3}, [%4];"
                 : "=r"(r0), "=r"(r1), "=r"(r2), "=r"(r3) : "r"(a));
}

// mma.sync m16n8k16 bf16 -> fp32, D += A*B
__device__ __forceinline__ void mma16816(float* d, u32 a0, u32 a1, u32 a2, u32 a3,
                                         u32 b0, u32 b1) {
    asm volatile(
        "mma.sync.aligned.m16n8k16.row.col.f32.bf16.bf16.f32 "
        "{%0,%1,%2,%3}, {%4,%5,%6,%7}, {%8,%9}, {%0,%1,%2,%3};"
        : "+f"(d[0]), "+f"(d[1]), "+f"(d[2]), "+f"(d[3])
        : "r"(a0), "r"(a1), "r"(a2), "r"(a3), "r"(b0), "r"(b1));
}

// ---------------------------------------------------------------------------
// Kernel A: Wh = h @ W (FFMA2), 32-row tiles (grid 512 for occupancy).
// Epilogue writes fp32 + bf16 hi/lo split.
// ---------------------------------------------------------------------------
__global__ void __launch_bounds__(128) wh_gemm(const float* __restrict__ h,
                                               const float* __restrict__ W) {
    __shared__ float hs[32][32];
    __shared__ float Ws[32][128];
    const int tid = threadIdx.x;
    const int tx = tid & 15, ty = tid >> 4;      // ty 0..7, 4 rows each
    const int i0 = blockIdx.x * 32;

    u64 acc[4][4];
    #pragma unroll
    for (int r = 0; r < 4; r++)
        #pragma unroll
        for (int c = 0; c < 4; c++) acc[r][c] = 0ULL;

    for (int k0 = 0; k0 < F_; k0 += 32) {
        #pragma unroll
        for (int p = 0; p < 2; p++) {
            int idx = tid + 128 * p;             // 256 float4
            int r = idx >> 3;
            int c4 = idx & 7;
            *(float4*)&hs[r][c4 * 4] =
                *(const float4*)&h[(i0 + r) * F_ + k0 + c4 * 4];
        }
        #pragma unroll
        for (int p = 0; p < 8; p++) {
            int idx = tid + 128 * p;
            int r = idx >> 5;
            int c4 = idx & 31;
            *(float4*)&Ws[r][c4 * 4] =
                *(const float4*)&W[(k0 + r) * F_ + c4 * 4];
        }
        __syncthreads();
        #pragma unroll
        for (int kk = 0; kk < 32; kk++) {
            u64 av[4];
            #pragma unroll
            for (int r = 0; r < 4; r++) av[r] = dup2(hs[ty * 4 + r][kk]);
            ulonglong2 wa = *(ulonglong2*)&Ws[kk][tx * 8];
            ulonglong2 wb = *(ulonglong2*)&Ws[kk][tx * 8 + 4];
            #pragma unroll
            for (int r = 0; r < 4; r++) {
                acc[r][0] = ffma2(av[r], wa.x, acc[r][0]);
                acc[r][1] = ffma2(av[r], wa.y, acc[r][1]);
                acc[r][2] = ffma2(av[r], wb.x, acc[r][2]);
                acc[r][3] = ffma2(av[r], wb.y, acc[r][3]);
            }
        }
        __syncthreads();
    }
    #pragma unroll
    for (int r = 0; r < 4; r++) {
        int row = i0 + ty * 4 + r;
        float v[8];
        #pragma unroll
        for (int c = 0; c < 4; c++) {
            float2 f = *(float2*)&acc[r][c];
            v[2 * c] = f.x; v[2 * c + 1] = f.y;
        }
        *(float4*)&g_Wh[row * F_ + tx * 8]     = make_float4(v[0], v[1], v[2], v[3]);
        *(float4*)&g_Wh[row * F_ + tx * 8 + 4] = make_float4(v[4], v[5], v[6], v[7]);
        __nv_bfloat162 H[4], L[4];
        #pragma unroll
        for (int c = 0; c < 4; c++) {
            float x = v[2 * c], y = v[2 * c + 1];
            H[c] = __float22bfloat162_rn(make_float2(x, y));
            float lx = x - __low2float(H[c]);
            float ly = y - __high2float(H[c]);
            L[c] = __float22bfloat162_rn(make_float2(lx, ly));
        }
        uint4 uh, ul;
        uh.x = *(u32*)&H[0]; uh.y = *(u32*)&H[1]; uh.z = *(u32*)&H[2]; uh.w = *(u32*)&H[3];
        ul.x = *(u32*)&L[0]; ul.y = *(u32*)&L[1]; ul.z = *(u32*)&L[2]; ul.w = *(u32*)&L[3];
        *(uint4*)&g_Whh[row * F_ + tx * 8] = uh;
        *(uint4*)&g_Whl[row * F_ + tx * 8] = ul;
    }
}

// ---------------------------------------------------------------------------
// Kernel B: s1/s2 = Wh·a1 / Wh·a2, plus transposed s2t[j][b].
// ---------------------------------------------------------------------------
__global__ void __launch_bounds__(256) compute_s(const float* __restrict__ a) {
    int row = blockIdx.x * 8 + (threadIdx.x >> 5);
    int lane = threadIdx.x & 31;
    float4 w  = *(const float4*)&g_Wh[row * F_ + lane * 4];
    float4 a1 = *(const float4*)&a[lane * 4];
    float4 a2 = *(const float4*)&a[F_ + lane * 4];
    float d1 = w.x * a1.x + w.y * a1.y + w.z * a1.z + w.w * a1.w;
    float d2 = w.x * a2.x + w.y * a2.y + w.z * a2.z + w.w * a2.w;
    #pragma unroll
    for (int o = 16; o > 0; o >>= 1) {
        d1 += __shfl_xor_sync(0xffffffffu, d1, o);
        d2 += __shfl_xor_sync(0xffffffffu, d2, o);
    }
    if (lane == 0) {
        g_s1[row] = d1;
        g_s2[row] = d2;
        int b = row >> 11;          // N_ = 2048
        int i = row & (N_ - 1);
        g_s2t[i * B_ + b] = d2;
    }
}

// ---------------------------------------------------------------------------
// Kernel B2: m2[b][i] = max over j with adj[i,j]>0 of s2[b][j].
// ---------------------------------------------------------------------------
__global__ void __launch_bounds__(256) row_max(const int* __restrict__ adj) {
    int i = blockIdx.x * 8 + (threadIdx.x >> 5);
    int lane = threadIdx.x & 31;
    float m[8];
    #pragma unroll
    for (int bb = 0; bb < 8; bb++) m[bb] = NEG_BIG;

    #pragma unroll 4
    for (int it = 0; it < N_ / 32; it++) {
        int j = it * 32 + lane;
        int ad = adj[i * N_ + j];
        if (ad > 0) {
            float4 v0 = *(const float4*)&g_s2t[j * B_];
            float4 v1 = *(const float4*)&g_s2t[j * B_ + 4];
            m[0] = fmaxf(m[0], v0.x); m[1] = fmaxf(m[1], v0.y);
            m[2] = fmaxf(m[2], v0.z); m[3] = fmaxf(m[3], v0.w);
            m[4] = fmaxf(m[4], v1.x); m[5] = fmaxf(m[5], v1.y);
            m[6] = fmaxf(m[6], v1.z); m[7] = fmaxf(m[7], v1.w);
        }
    }
    #pragma unroll
    for (int o = 16; o > 0; o >>= 1)
        #pragma unroll
        for (int bb = 0; bb < 8; bb++)
            m[bb] = fmaxf(m[bb], __shfl_xor_sync(0xffffffffu, m[bb], o));
    if (lane == 0) {
        #pragma unroll
        for (int bb = 0; bb < 8; bb++) g_m2[bb * N_ + i] = m[bb];
    }
}

// ---------------------------------------------------------------------------
// Kernel C: split-j masked softmax aggregation, mma.sync bf16x3.
// N-split warp layout: each warp computes all 64 rows x its 32-col strip.
// B fragments loaded once per ks and reused over 4 m-tiles (48 LDSM/tile/warp).
//
// smem layout (bytes), strides padded for conflict-free ldmatrix:
//   WThi [64][136 bf16] stride 272B  @ 0      (17408)
//   WTlo                              @ 17408 (17408)
//   Phi  [64][72 bf16]  stride 144B  @ 34816 (9216)
//   Plo                               @ 44032 (9216)
//   s1s/s2s/Ms fp32[64]               @ 53248/53504/53760
// ---------------------------------------------------------------------------
#define OFF_WTHI 0
#define OFF_WTLO 17408
#define OFF_PHI  34816
#define OFF_PLO  44032
#define OFF_S1   53248
#define OFF_S2   53504
#define OFF_MS   53760
#define SMEM_C   54016

__global__ void __launch_bounds__(128, 4) gat_attn(const int* __restrict__ adj) {
    extern __shared__ char smc[];
    float* s1s = (float*)(smc + OFF_S1);
    float* s2s = (float*)(smc + OFF_S2);
    float* Ms  = (float*)(smc + OFF_MS);

    const int tid = threadIdx.x;
    const int lane = tid & 31;
    const int w = tid >> 5;                      // warp 0..3
    const int b = blockIdx.y;
    const int s = blockIdx.z;
    const int i0 = blockIdx.x * 64;

    const u32 sbase = (u32)__cvta_generic_to_shared(smc);

    if (tid < 64) {
        float s1 = g_s1[b * N_ + i0 + tid];
        float m2 = g_m2[b * N_ + i0 + tid];
        s1s[tid] = s1;
        float Mi;
        if (m2 < -8.0e15f) {
            Mi = NEG_BIG;                        // empty row -> uniform softmax
        } else {
            float x = s1 + m2;
            Mi = fmaxf(x, ALPHA * x);            // lr monotone -> row max
        }
        Ms[tid] = Mi;
    }

    float acc[4][4][4];                          // [m-tile][n8][quad]
    #pragma unroll
    for (int m = 0; m < 4; m++)
        #pragma unroll
        for (int n = 0; n < 4; n++)
            #pragma unroll
            for (int c = 0; c < 4; c++) acc[m][n][c] = 0.f;
    float lacc[8];                               // row-sum partials, row g+8k
    #pragma unroll
    for (int k = 0; k < 8; k++) lacc[k] = 0.f;

    const int g  = tid >> 4;                     // 0..7: score-phase row group
    const int jq = (tid & 15) * 4;               // score-phase j quad

    // ldmatrix lane-invariant offsets
    const int lg = lane >> 3, lr = lane & 7;
    const u32 aoff = (u32)(((lg & 1) * 8 + lr) * 144 + (lg >> 1) * 16);
    const u32 boff = (u32)(((lg & 1) * 8 + lr) * 272 + (lg >> 1) * 16);

    const int jt0 = s * (N_ / 64 / S_);          // 8 tiles per split
    const int jt1 = jt0 + (N_ / 64 / S_);

    for (int jt = jt0; jt < jt1; jt++) {
        const int j0 = jt * 64;

        // ---- fill: WThi/WTlo tiles (bf16, straight copy) + s2s ----
        {
            const uint4* srcH = (const uint4*)&g_Whh[(b * N_ + j0) * F_];
            const uint4* srcL = (const uint4*)&g_Whl[(b * N_ + j0) * F_];
            #pragma unroll
            for (int p = 0; p < 8; p++) {
                int idx = tid + 128 * p;         // 1024 uint4 (64 rows x 16)
                int r = idx >> 4;
                int c16 = idx & 15;
                *(uint4*)(smc + OFF_WTHI + r * 272 + c16 * 16) = srcH[r * 16 + c16];
                *(uint4*)(smc + OFF_WTLO + r * 272 + c16 * 16) = srcL[r * 16 + c16];
            }
            if (tid < 64) s2s[tid] = g_s2[b * N_ + j0 + tid];
        }
        __syncthreads();

        // ---- scores + exp + bf16 hi/lo split + register l-sums ----
        {
            float4 s2v = *(const float4*)&s2s[jq];
            const int* arow = adj + (long)(i0 + g) * N_ + j0 + jq;
            #pragma unroll
            for (int k = 0; k < 8; k++) {
                int i = g + 8 * k;
                int4 ad = *(const int4*)&arow[8 * k * N_];
                float s1v = s1s[i];
                float Mi  = Ms[i];
                float x0 = s1v + s2v.x, x1 = s1v + s2v.y;
                float x2 = s1v + s2v.z, x3 = s1v + s2v.w;
                float l0 = fmaxf(x0, ALPHA * x0), l1 = fmaxf(x1, ALPHA * x1);
                float l2 = fmaxf(x2, ALPHA * x2), l3 = fmaxf(x3, ALPHA * x3);
                float p0 = __expf(((ad.x > 0) ? l0 : NEG_BIG) - Mi);
                float p1 = __expf(((ad.y > 0) ? l1 : NEG_BIG) - Mi);
                float p2 = __expf(((ad.z > 0) ? l2 : NEG_BIG) - Mi);
                float p3 = __expf(((ad.w > 0) ? l3 : NEG_BIG) - Mi);
                lacc[k] += (p0 + p1) + (p2 + p3);
                __nv_bfloat162 h01 = __float22bfloat162_rn(make_float2(p0, p1));
                __nv_bfloat162 h23 = __float22bfloat162_rn(make_float2(p2, p3));
                float q0 = p0 - __low2float(h01),  q1 = p1 - __high2float(h01);
                float q2 = p2 - __low2float(h23),  q3 = p3 - __high2float(h23);
                __nv_bfloat162 l01 = __float22bfloat162_rn(make_float2(q0, q1));
                __nv_bfloat162 l23 = __float22bfloat162_rn(make_float2(q2, q3));
                uint2 uh, ulv;
                uh.x = *(u32*)&h01; uh.y = *(u32*)&h23;
                ulv.x = *(u32*)&l01; ulv.y = *(u32*)&l23;
                *(uint2*)(smc + OFF_PHI + i * 144 + jq * 2) = uh;
                *(uint2*)(smc + OFF_PLO + i * 144 + jq * 2) = ulv;
            }
        }
        __syncthreads();

        // ---- aggregation: P(64x64) @ Wh(64x128), N-split warps ----
        {
            #pragma unroll
            for (int ks = 0; ks < 4; ks++) {
                // B fragments for this warp's 32-col strip (2 n16 groups)
                u32 bh[2][4], bl[2][4];
                const u32 bbase = sbase + OFF_WTHI + (u32)(ks * 16 * 272)
                                + boff + (u32)(w * 64);
                #pragma unroll
                for (int ng = 0; ng < 2; ng++) {
                    u32 bb = bbase + ng * 32;
                    ldsm4t(bh[ng][0], bh[ng][1], bh[ng][2], bh[ng][3], bb);
                    ldsm4t(bl[ng][0], bl[ng][1], bl[ng][2], bl[ng][3],
                           bb + (OFF_WTLO - OFF_WTHI));
                }
                #pragma unroll
                for (int m = 0; m < 4; m++) {
                    u32 ah0, ah1, ah2, ah3, al0, al1, al2, al3;
                    u32 aA = sbase + OFF_PHI + (u32)(m * 16 * 144) + aoff
                           + (u32)(ks * 32);
                    ldsm4(ah0, ah1, ah2, ah3, aA);
                    ldsm4(al0, al1, al2, al3, aA + (OFF_PLO - OFF_PHI));
                    #pragma unroll
                    for (int ng = 0; ng < 2; ng++) {
                        mma16816(acc[m][2 * ng],     ah0, ah1, ah2, ah3, bh[ng][0], bh[ng][1]);
                        mma16816(acc[m][2 * ng],     ah0, ah1, ah2, ah3, bl[ng][0], bl[ng][1]);
                        mma16816(acc[m][2 * ng],     al0, al1, al2, al3, bh[ng][0], bh[ng][1]);
                        mma16816(acc[m][2 * ng + 1], ah0, ah1, ah2, ah3, bh[ng][2], bh[ng][3]);
                        mma16816(acc[m][2 * ng + 1], ah0, ah1, ah2, ah3, bl[ng][2], bl[ng][3]);
                        mma16816(acc[m][2 * ng + 1], al0, al1, al2, al3, bh[ng][2], bh[ng][3]);
                    }
                }
            }
        }
        __syncthreads();
    }

    // ---- partial l: reduce lacc over the 16-lane row groups ----
    #pragma unroll
    for (int k = 0; k < 8; k++) {
        float v = lacc[k];
        v += __shfl_xor_sync(0xffffffffu, v, 1);
        v += __shfl_xor_sync(0xffffffffu, v, 2);
        v += __shfl_xor_sync(0xffffffffu, v, 4);
        v += __shfl_xor_sync(0xffffffffu, v, 8);
        if ((tid & 15) == 0)
            g_pl[(s * B_ + b) * N_ + i0 + g + 8 * k] = v;
    }

    // ---- partial accumulator (unnormalized) ----
    {
        float* pout = g_pacc + ((long)(s * B_ + b) * N_ + i0) * F_;
        const int rr = lane >> 2;
        const int c0 = w * 32 + 2 * (lane & 3);
        #pragma unroll
        for (int m = 0; m < 4; m++) {
            #pragma unroll
            for (int gq = 0; gq < 4; gq++) {
                int row0 = 16 * m + rr;
                int col = c0 + 8 * gq;
                *(float2*)&pout[row0 * F_ + col] =
                    make_float2(acc[m][gq][0], acc[m][gq][1]);
                *(float2*)&pout[(row0 + 8) * F_ + col] =
                    make_float2(acc[m][gq][2], acc[m][gq][3]);
            }
        }
    }
}

// ---------------------------------------------------------------------------
// Kernel D: reduce splits. out[b,i,f] = sum_s pacc / sum_s pl.
// ---------------------------------------------------------------------------
__global__ void __launch_bounds__(256) reduce_splits(float* __restrict__ out) {
    const long idx = (long)blockIdx.x * 256 + threadIdx.x;   // float4 index
    const long row = idx >> 5;                               // F_/4 = 32 per row
    const long NBF = (long)B_ * N_ * F_ / 4;                 // float4 per split

    float l = 0.f;
    #pragma unroll
    for (int s = 0; s < S_; s++) l += g_pl[s * B_ * N_ + row];
    float inv = 1.f / l;

    float4 acc = make_float4(0.f, 0.f, 0.f, 0.f);
    const float4* pa = (const float4*)g_pacc;
    #pragma unroll
    for (int s = 0; s < S_; s++) {
        float4 v = pa[s * NBF + idx];
        acc.x += v.x; acc.y += v.y; acc.z += v.z; acc.w += v.w;
    }
    float4 o = make_float4(acc.x * inv, acc.y * inv, acc.z * inv, acc.w * inv);
    ((float4*)out)[idx] = o;
}

// ---------------------------------------------------------------------------
extern "C" void kernel_launch(void* const* d_in, const int* in_sizes, int n_in,
                              void* d_out, int out_size) {
    const float* h   = (const float*)d_in[0];   // [8,2048,128]
    const int*   adj = (const int*)d_in[1];     // [2048,2048]
    const float* W   = (const float*)d_in[2];   // [128,128]
    const float* a   = (const float*)d_in[3];   // [256,1]
    float* out = (float*)d_out;                 // [8,2048,128]

    (void)in_sizes; (void)n_in; (void)out_size;

    static bool attr_set = false;
    if (!attr_set) {
        cudaFuncSetAttribute(gat_attn,
                             cudaFuncAttributeMaxDynamicSharedMemorySize,
                             SMEM_C);
        attr_set = true;
    }

    wh_gemm<<<(B_ * N_) / 32, 128>>>(h, W);
    compute_s<<<(B_ * N_) / 8, 256>>>(a);
    row_max<<<N_ / 8, 256>>>(adj);
    gat_attn<<<dim3(N_ / 64, B_, S_), 128, SMEM_C>>>(adj);
    reduce_splits<<<(B_ * N_ * F_ / 4) / 256, 256>>>(out);
}

// round 9
// speedup vs baseline: 2.3934x; 1.0337x over previous
#include <cuda_runtime.h>
#include <cuda_bf16.h>

#define ALPHA   0.2f
#define NEG_BIG -9.0e15f

#define B_   8
#define N_   2048
#define F_   128
#define S_   4            // j-splits per (batch, i-tile)

typedef unsigned long long u64;
typedef unsigned int u32;

// Scratch (device globals — no allocation allowed in kernel_launch)
__device__ float g_Wh[B_ * N_ * F_];            // fp32, 8 MB (for compute_s)
__device__ __nv_bfloat16 g_Whh[B_ * N_ * F_];   // bf16 hi, 4 MB
__device__ __nv_bfloat16 g_Whl[B_ * N_ * F_];   // bf16 lo (residual), 4 MB
__device__ float g_s1[B_ * N_];
__device__ float g_s2[B_ * N_];
__device__ float g_s2t[N_ * B_];                // transposed s2: [j][b]
__device__ float g_m2[B_ * N_];                 // masked row-max of s2
__device__ u64   g_mask[N_ * (N_ / 64)];        // adjacency bitmask, 512 KB
__device__ float g_pacc[S_ * B_ * N_ * F_];     // partial aggregates, 32 MB
__device__ float g_pl[S_ * B_ * N_];            // partial l sums

// Packed fp32x2 FMA (sm_103a FFMA2): d = a*b + c element-wise.
__device__ __forceinline__ u64 ffma2(u64 a, u64 b, u64 c) {
    u64 d;
    asm("fma.rn.f32x2 %0, %1, %2, %3;" : "=l"(d) : "l"(a), "l"(b), "l"(c));
    return d;
}
__device__ __forceinline__ u64 dup2(float x) {
    u64 d;
    u32 xi = __float_as_uint(x);
    asm("mov.b64 %0, {%1, %2};" : "=l"(d) : "r"(xi), "r"(xi));
    return d;
}

// ldmatrix x4 (non-transposed / transposed)
__device__ __forceinline__ void ldsm4(u32& r0, u32& r1, u32& r2, u32& r3, u32 a) {
    asm volatile("ldmatrix.sync.aligned.m8n8.x4.shared.b16 {%0,%1,%2,%3}, [%4];"
                 : "=r"(r0), "=r"(r1), "=r"(r2), "=r"(r3) : "r"(a));
}
__device__ __forceinline__ void ldsm4t(u32& r0, u32& r1, u32& r2, u32& r3, u32 a) {
    asm volatile("ldmatrix.sync.aligned.m8n8.x4.trans.shared.b16 {%0,%1,%2,%3}, [%4];"
                 : "=r"(r0), "=r"(r1), "=r"(r2), "=r"(r3) : "r"(a));
}

// mma.sync m16n8k16 bf16 -> fp32, D += A*B
__device__ __forceinline__ void mma16816(float* d, u32 a0, u32 a1, u32 a2, u32 a3,
                                         u32 b0, u32 b1) {
    asm volatile(
        "mma.sync.aligned.m16n8k16.row.col.f32.bf16.bf16.f32 "
        "{%0,%1,%2,%3}, {%4,%5,%6,%7}, {%8,%9}, {%0,%1,%2,%3};"
        : "+f"(d[0]), "+f"(d[1]), "+f"(d[2]), "+f"(d[3])
        : "r"(a0), "r"(a1), "r"(a2), "r"(a3), "r"(b0), "r"(b1));
}

// cp.async 16B
__device__ __forceinline__ void cpa16(u32 dst, const void* src) {
    asm volatile("cp.async.cg.shared.global [%0], [%1], 16;"
                 :: "r"(dst), "l"(src));
}

// ---------------------------------------------------------------------------
// Kernel A: Wh = h @ W (FFMA2), 32-row tiles.
// Epilogue writes fp32 + bf16 hi/lo split.
// ---------------------------------------------------------------------------
__global__ void __launch_bounds__(128) wh_gemm(const float* __restrict__ h,
                                               const float* __restrict__ W) {
    __shared__ float hs[32][32];
    __shared__ float Ws[32][128];
    const int tid = threadIdx.x;
    const int tx = tid & 15, ty = tid >> 4;      // ty 0..7, 4 rows each
    const int i0 = blockIdx.x * 32;

    u64 acc[4][4];
    #pragma unroll
    for (int r = 0; r < 4; r++)
        #pragma unroll
        for (int c = 0; c < 4; c++) acc[r][c] = 0ULL;

    for (int k0 = 0; k0 < F_; k0 += 32) {
        #pragma unroll
        for (int p = 0; p < 2; p++) {
            int idx = tid + 128 * p;             // 256 float4
            int r = idx >> 3;
            int c4 = idx & 7;
            *(float4*)&hs[r][c4 * 4] =
                *(const float4*)&h[(i0 + r) * F_ + k0 + c4 * 4];
        }
        #pragma unroll
        for (int p = 0; p < 8; p++) {
            int idx = tid + 128 * p;
            int r = idx >> 5;
            int c4 = idx & 31;
            *(float4*)&Ws[r][c4 * 4] =
                *(const float4*)&W[(k0 + r) * F_ + c4 * 4];
        }
        __syncthreads();
        #pragma unroll
        for (int kk = 0; kk < 32; kk++) {
            u64 av[4];
            #pragma unroll
            for (int r = 0; r < 4; r++) av[r] = dup2(hs[ty * 4 + r][kk]);
            ulonglong2 wa = *(ulonglong2*)&Ws[kk][tx * 8];
            ulonglong2 wb = *(ulonglong2*)&Ws[kk][tx * 8 + 4];
            #pragma unroll
            for (int r = 0; r < 4; r++) {
                acc[r][0] = ffma2(av[r], wa.x, acc[r][0]);
                acc[r][1] = ffma2(av[r], wa.y, acc[r][1]);
                acc[r][2] = ffma2(av[r], wb.x, acc[r][2]);
                acc[r][3] = ffma2(av[r], wb.y, acc[r][3]);
            }
        }
        __syncthreads();
    }
    #pragma unroll
    for (int r = 0; r < 4; r++) {
        int row = i0 + ty * 4 + r;
        float v[8];
        #pragma unroll
        for (int c = 0; c < 4; c++) {
            float2 f = *(float2*)&acc[r][c];
            v[2 * c] = f.x; v[2 * c + 1] = f.y;
        }
        *(float4*)&g_Wh[row * F_ + tx * 8]     = make_float4(v[0], v[1], v[2], v[3]);
        *(float4*)&g_Wh[row * F_ + tx * 8 + 4] = make_float4(v[4], v[5], v[6], v[7]);
        __nv_bfloat162 H[4], L[4];
        #pragma unroll
        for (int c = 0; c < 4; c++) {
            float x = v[2 * c], y = v[2 * c + 1];
            H[c] = __float22bfloat162_rn(make_float2(x, y));
            float lx = x - __low2float(H[c]);
            float ly = y - __high2float(H[c]);
            L[c] = __float22bfloat162_rn(make_float2(lx, ly));
        }
        uint4 uh, ul;
        uh.x = *(u32*)&H[0]; uh.y = *(u32*)&H[1]; uh.z = *(u32*)&H[2]; uh.w = *(u32*)&H[3];
        ul.x = *(u32*)&L[0]; ul.y = *(u32*)&L[1]; ul.z = *(u32*)&L[2]; ul.w = *(u32*)&L[3];
        *(uint4*)&g_Whh[row * F_ + tx * 8] = uh;
        *(uint4*)&g_Whl[row * F_ + tx * 8] = ul;
    }
}

// ---------------------------------------------------------------------------
// Kernel A2: build adjacency bitmask. One warp per row, 16 iterations.
// g_mask[i*32 + w] bit j = (adj[i][w*64 + j] > 0).
// ---------------------------------------------------------------------------
__global__ void __launch_bounds__(256) build_mask(const int* __restrict__ adj) {
    const int i = (blockIdx.x * 256 + threadIdx.x) >> 5;     // row
    const int lane = threadIdx.x & 31;
    #pragma unroll 4
    for (int it = 0; it < 16; it++) {
        int j = it * 128 + lane * 4;
        int4 v = *(const int4*)&adj[(long)i * N_ + j];
        u32 nib = (u32)(v.x > 0) | ((u32)(v.y > 0) << 1)
                | ((u32)(v.z > 0) << 2) | ((u32)(v.w > 0) << 3);
        u64 word = (u64)nib << (4 * (lane & 15));
        #pragma unroll
        for (int o = 1; o < 16; o <<= 1)
            word |= __shfl_xor_sync(0xffffffffu, word, o);
        if ((lane & 15) == 0)
            g_mask[i * 32 + it * 2 + (lane >> 4)] = word;
    }
}

// ---------------------------------------------------------------------------
// Kernel B: s1/s2 = Wh·a1 / Wh·a2, plus transposed s2t[j][b].
// ---------------------------------------------------------------------------
__global__ void __launch_bounds__(256) compute_s(const float* __restrict__ a) {
    int row = blockIdx.x * 8 + (threadIdx.x >> 5);
    int lane = threadIdx.x & 31;
    float4 w  = *(const float4*)&g_Wh[row * F_ + lane * 4];
    float4 a1 = *(const float4*)&a[lane * 4];
    float4 a2 = *(const float4*)&a[F_ + lane * 4];
    float d1 = w.x * a1.x + w.y * a1.y + w.z * a1.z + w.w * a1.w;
    float d2 = w.x * a2.x + w.y * a2.y + w.z * a2.z + w.w * a2.w;
    #pragma unroll
    for (int o = 16; o > 0; o >>= 1) {
        d1 += __shfl_xor_sync(0xffffffffu, d1, o);
        d2 += __shfl_xor_sync(0xffffffffu, d2, o);
    }
    if (lane == 0) {
        g_s1[row] = d1;
        g_s2[row] = d2;
        int b = row >> 11;          // N_ = 2048
        int i = row & (N_ - 1);
        g_s2t[i * B_ + b] = d2;
    }
}

// ---------------------------------------------------------------------------
// Kernel B2: m2[b][i] = max over j with adj[i,j]>0 of s2[b][j].
// ---------------------------------------------------------------------------
__global__ void __launch_bounds__(256) row_max(const int* __restrict__ adj) {
    int i = blockIdx.x * 8 + (threadIdx.x >> 5);
    int lane = threadIdx.x & 31;
    float m[8];
    #pragma unroll
    for (int bb = 0; bb < 8; bb++) m[bb] = NEG_BIG;

    #pragma unroll 4
    for (int it = 0; it < N_ / 32; it++) {
        int j = it * 32 + lane;
        int ad = adj[i * N_ + j];
        if (ad > 0) {
            float4 v0 = *(const float4*)&g_s2t[j * B_];
            float4 v1 = *(const float4*)&g_s2t[j * B_ + 4];
            m[0] = fmaxf(m[0], v0.x); m[1] = fmaxf(m[1], v0.y);
            m[2] = fmaxf(m[2], v0.z); m[3] = fmaxf(m[3], v0.w);
            m[4] = fmaxf(m[4], v1.x); m[5] = fmaxf(m[5], v1.y);
            m[6] = fmaxf(m[6], v1.z); m[7] = fmaxf(m[7], v1.w);
        }
    }
    #pragma unroll
    for (int o = 16; o > 0; o >>= 1)
        #pragma unroll
        for (int bb = 0; bb < 8; bb++)
            m[bb] = fmaxf(m[bb], __shfl_xor_sync(0xffffffffu, m[bb], o));
    if (lane == 0) {
        #pragma unroll
        for (int bb = 0; bb < 8; bb++) g_m2[bb * N_ + i] = m[bb];
    }
}

// ---------------------------------------------------------------------------
// Kernel C: split-j masked softmax aggregation, mma.sync bf16x3.
// Pipelined: cp.async WT fills overlap the score phase; adjacency via
// L2-resident bitmask (broadcast u64 loads).
//
// smem layout (bytes), strides padded for conflict-free ldmatrix:
//   WThi [64][136 bf16] stride 272B  @ 0      (17408)
//   WTlo                              @ 17408 (17408)
//   Phi  [64][72 bf16]  stride 144B  @ 34816 (9216)
//   Plo                               @ 44032 (9216)
//   s1s/Ms fp32[64]                   @ 53248/53504
// ---------------------------------------------------------------------------
#define OFF_WTHI 0
#define OFF_WTLO 17408
#define OFF_PHI  34816
#define OFF_PLO  44032
#define OFF_S1   53248
#define OFF_MS   53504
#define SMEM_C   53760

__global__ void __launch_bounds__(128, 4) gat_attn() {
    extern __shared__ char smc[];
    float* s1s = (float*)(smc + OFF_S1);
    float* Ms  = (float*)(smc + OFF_MS);

    const int tid = threadIdx.x;
    const int lane = tid & 31;
    const int w = tid >> 5;                      // warp 0..3
    const int b = blockIdx.y;
    const int s = blockIdx.z;
    const int i0 = blockIdx.x * 64;

    const u32 sbase = (u32)__cvta_generic_to_shared(smc);

    if (tid < 64) {
        float s1 = g_s1[b * N_ + i0 + tid];
        float m2 = g_m2[b * N_ + i0 + tid];
        s1s[tid] = s1;
        float Mi;
        if (m2 < -8.0e15f) {
            Mi = NEG_BIG;                        // empty row -> uniform softmax
        } else {
            float x = s1 + m2;
            Mi = fmaxf(x, ALPHA * x);            // lr monotone -> row max
        }
        Ms[tid] = Mi;
    }
    __syncthreads();

    float acc[4][4][4];                          // [m-tile][n8][quad]
    #pragma unroll
    for (int m = 0; m < 4; m++)
        #pragma unroll
        for (int n = 0; n < 4; n++)
            #pragma unroll
            for (int c = 0; c < 4; c++) acc[m][n][c] = 0.f;
    float lacc[8];                               // row-sum partials, row g+8k
    #pragma unroll
    for (int k = 0; k < 8; k++) lacc[k] = 0.f;

    const int g  = tid >> 4;                     // 0..7: score-phase row group
    const int jq = (tid & 15) * 4;               // score-phase j quad

    // ldmatrix lane-invariant offsets
    const int lg = lane >> 3, lr = lane & 7;
    const u32 aoff = (u32)(((lg & 1) * 8 + lr) * 144 + (lg >> 1) * 16);
    const u32 boff = (u32)(((lg & 1) * 8 + lr) * 272 + (lg >> 1) * 16);

    const int jt0 = s * (N_ / 64 / S_);          // 8 tiles per split
    const int jt1 = jt0 + (N_ / 64 / S_);

    for (int jt = jt0; jt < jt1; jt++) {
        const int j0 = jt * 64;

        // ---- issue async WT fills (overlap with score phase) ----
        {
            const uint4* srcH = (const uint4*)&g_Whh[(b * N_ + j0) * F_];
            const uint4* srcL = (const uint4*)&g_Whl[(b * N_ + j0) * F_];
            #pragma unroll
            for (int p = 0; p < 8; p++) {
                int idx = tid + 128 * p;         // 1024 uint4 (64 rows x 16)
                int r = idx >> 4;
                int c16 = idx & 15;
                u32 doff = (u32)(r * 272 + c16 * 16);
                cpa16(sbase + OFF_WTHI + doff, srcH + r * 16 + c16);
                cpa16(sbase + OFF_WTLO + doff, srcL + r * 16 + c16);
            }
            asm volatile("cp.async.commit_group;");
        }

        // ---- scores + exp + bf16 hi/lo split + register l-sums ----
        {
            // mask words: broadcast across 16-lane groups, L2-resident
            u64 mw[8];
            #pragma unroll
            for (int k = 0; k < 8; k++)
                mw[k] = g_mask[(i0 + g + 8 * k) * 32 + jt];
            float4 s2v = *(const float4*)&g_s2[b * N_ + j0 + jq];
            #pragma unroll
            for (int k = 0; k < 8; k++) {
                int i = g + 8 * k;
                u32 nib = (u32)(mw[k] >> jq) & 15u;
                float s1v = s1s[i];
                float Mi  = Ms[i];
                float x0 = s1v + s2v.x, x1 = s1v + s2v.y;
                float x2 = s1v + s2v.z, x3 = s1v + s2v.w;
                float l0 = fmaxf(x0, ALPHA * x0), l1 = fmaxf(x1, ALPHA * x1);
                float l2 = fmaxf(x2, ALPHA * x2), l3 = fmaxf(x3, ALPHA * x3);
                float p0 = __expf(((nib & 1u) ? l0 : NEG_BIG) - Mi);
                float p1 = __expf(((nib & 2u) ? l1 : NEG_BIG) - Mi);
                float p2 = __expf(((nib & 4u) ? l2 : NEG_BIG) - Mi);
                float p3 = __expf(((nib & 8u) ? l3 : NEG_BIG) - Mi);
                lacc[k] += (p0 + p1) + (p2 + p3);
                __nv_bfloat162 h01 = __float22bfloat162_rn(make_float2(p0, p1));
                __nv_bfloat162 h23 = __float22bfloat162_rn(make_float2(p2, p3));
                float q0 = p0 - __low2float(h01),  q1 = p1 - __high2float(h01);
                float q2 = p2 - __low2float(h23),  q3 = p3 - __high2float(h23);
                __nv_bfloat162 l01 = __float22bfloat162_rn(make_float2(q0, q1));
                __nv_bfloat162 l23 = __float22bfloat162_rn(make_float2(q2, q3));
                uint2 uh, ulv;
                uh.x = *(u32*)&h01; uh.y = *(u32*)&h23;
                ulv.x = *(u32*)&l01; ulv.y = *(u32*)&l23;
                *(uint2*)(smc + OFF_PHI + i * 144 + jq * 2) = uh;
                *(uint2*)(smc + OFF_PLO + i * 144 + jq * 2) = ulv;
            }
        }

        asm volatile("cp.async.wait_group 0;");
        __syncthreads();

        // ---- aggregation: P(64x64) @ Wh(64x128), N-split warps ----
        {
            #pragma unroll
            for (int ks = 0; ks < 4; ks++) {
                // B fragments for this warp's 32-col strip (2 n16 groups)
                u32 bh[2][4], bl[2][4];
                const u32 bbase = sbase + OFF_WTHI + (u32)(ks * 16 * 272)
                                + boff + (u32)(w * 64);
                #pragma unroll
                for (int ng = 0; ng < 2; ng++) {
                    u32 bb = bbase + ng * 32;
                    ldsm4t(bh[ng][0], bh[ng][1], bh[ng][2], bh[ng][3], bb);
                    ldsm4t(bl[ng][0], bl[ng][1], bl[ng][2], bl[ng][3],
                           bb + (OFF_WTLO - OFF_WTHI));
                }
                #pragma unroll
                for (int m = 0; m < 4; m++) {
                    u32 ah0, ah1, ah2, ah3, al0, al1, al2, al3;
                    u32 aA = sbase + OFF_PHI + (u32)(m * 16 * 144) + aoff
                           + (u32)(ks * 32);
                    ldsm4(ah0, ah1, ah2, ah3, aA);
                    ldsm4(al0, al1, al2, al3, aA + (OFF_PLO - OFF_PHI));
                    #pragma unroll
                    for (int ng = 0; ng < 2; ng++) {
                        mma16816(acc[m][2 * ng],     ah0, ah1, ah2, ah3, bh[ng][0], bh[ng][1]);
                        mma16816(acc[m][2 * ng],     ah0, ah1, ah2, ah3, bl[ng][0], bl[ng][1]);
                        mma16816(acc[m][2 * ng],     al0, al1, al2, al3, bh[ng][0], bh[ng][1]);
                        mma16816(acc[m][2 * ng + 1], ah0, ah1, ah2, ah3, bh[ng][2], bh[ng][3]);
                        mma16816(acc[m][2 * ng + 1], ah0, ah1, ah2, ah3, bl[ng][2], bl[ng][3]);
                        mma16816(acc[m][2 * ng + 1], al0, al1, al2, al3, bh[ng][2], bh[ng][3]);
                    }
                }
            }
        }
        __syncthreads();
    }

    // ---- partial l: reduce lacc over the 16-lane row groups ----
    #pragma unroll
    for (int k = 0; k < 8; k++) {
        float v = lacc[k];
        v += __shfl_xor_sync(0xffffffffu, v, 1);
        v += __shfl_xor_sync(0xffffffffu, v, 2);
        v += __shfl_xor_sync(0xffffffffu, v, 4);
        v += __shfl_xor_sync(0xffffffffu, v, 8);
        if ((tid & 15) == 0)
            g_pl[(s * B_ + b) * N_ + i0 + g + 8 * k] = v;
    }

    // ---- partial accumulator (unnormalized) ----
    {
        float* pout = g_pacc + ((long)(s * B_ + b) * N_ + i0) * F_;
        const int rr = lane >> 2;
        const int c0 = w * 32 + 2 * (lane & 3);
        #pragma unroll
        for (int m = 0; m < 4; m++) {
            #pragma unroll
            for (int gq = 0; gq < 4; gq++) {
                int row0 = 16 * m + rr;
                int col = c0 + 8 * gq;
                *(float2*)&pout[row0 * F_ + col] =
                    make_float2(acc[m][gq][0], acc[m][gq][1]);
                *(float2*)&pout[(row0 + 8) * F_ + col] =
                    make_float2(acc[m][gq][2], acc[m][gq][3]);
            }
        }
    }
}

// ---------------------------------------------------------------------------
// Kernel D: reduce splits. out[b,i,f] = sum_s pacc / sum_s pl.
// ---------------------------------------------------------------------------
__global__ void __launch_bounds__(256) reduce_splits(float* __restrict__ out) {
    const long idx = (long)blockIdx.x * 256 + threadIdx.x;   // float4 index
    const long row = idx >> 5;                               // F_/4 = 32 per row
    const long NBF = (long)B_ * N_ * F_ / 4;                 // float4 per split

    float l = 0.f;
    #pragma unroll
    for (int s = 0; s < S_; s++) l += g_pl[s * B_ * N_ + row];
    float inv = 1.f / l;

    float4 acc = make_float4(0.f, 0.f, 0.f, 0.f);
    const float4* pa = (const float4*)g_pacc;
    #pragma unroll
    for (int s = 0; s < S_; s++) {
        float4 v = pa[s * NBF + idx];
        acc.x += v.x; acc.y += v.y; acc.z += v.z; acc.w += v.w;
    }
    float4 o = make_float4(acc.x * inv, acc.y * inv, acc.z * inv, acc.w * inv);
    ((float4*)out)[idx] = o;
}

// ---------------------------------------------------------------------------
extern "C" void kernel_launch(void* const* d_in, const int* in_sizes, int n_in,
                              void* d_out, int out_size) {
    const float* h   = (const float*)d_in[0];   // [8,2048,128]
    const int*   adj = (const int*)d_in[1];     // [2048,2048]
    const float* W   = (const float*)d_in[2];   // [128,128]
    const float* a   = (const float*)d_in[3];   // [256,1]
    float* out = (float*)d_out;                 // [8,2048,128]

    (void)in_sizes; (void)n_in; (void)out_size;

    static bool attr_set = false;
    if (!attr_set) {
        cudaFuncSetAttribute(gat_attn,
                             cudaFuncAttributeMaxDynamicSharedMemorySize,
                             SMEM_C);
        attr_set = true;
    }

    wh_gemm<<<(B_ * N_) / 32, 128>>>(h, W);
    build_mask<<<N_ / 8, 256>>>(adj);
    compute_s<<<(B_ * N_) / 8, 256>>>(a);
    row_max<<<N_ / 8, 256>>>(adj);
    gat_attn<<<dim3(N_ / 64, B_, S_), 128, SMEM_C>>>();
    reduce_splits<<<(B_ * N_ * F_ / 4) / 256, 256>>>(out);
}